// round 1
// baseline (speedup 1.0000x reference)
#include <cuda_runtime.h>
#include <math.h>
#include <math_constants.h>

// Problem constants (Qwen3 MoE block: B=1, S=1024, H=2048, E=64, I=768, top_k=8)
constexpr int T = 1024;
constexpr int H = 2048;
constexpr int E = 64;
constexpr int I = 768;
constexpr int TOPK = 8;
constexpr int NSLOT = T * TOPK;  // 8192, exact (every token has exactly 8 experts)

// ---------------- scratch (device globals; no runtime allocation) -------------
__device__ int   g_topk_idx[NSLOT];
__device__ float g_topk_w[NSLOT];
__device__ int   g_counts[E];
__device__ int   g_offsets[E + 1];
__device__ int   g_fill[E];
__device__ int   g_slot_token[NSLOT];
__device__ float g_slot_w[NSLOT];
__device__ float g_gbuf[(size_t)NSLOT * I];  // gate-proj output, then fused act
__device__ float g_ubuf[(size_t)NSLOT * I];  // up-proj output

// ---------------- init: zero counters ----------------------------------------
__global__ void init_kernel() {
    int i = threadIdx.x;
    if (i < E) { g_counts[i] = 0; g_fill[i] = 0; }
}

// ---------------- gating: logits -> top-8 -> softmax renorm -------------------
__global__ __launch_bounds__(256) void gate_kernel(const float* __restrict__ x,
                                                   const float* __restrict__ gw) {
    __shared__ float xs[H];
    __shared__ float logits[E];
    int t = blockIdx.x;
    const float* xr = x + (size_t)t * H;
    for (int i = threadIdx.x; i < H; i += 256) xs[i] = xr[i];
    __syncthreads();

    int warp = threadIdx.x >> 5, lane = threadIdx.x & 31;
    // 8 warps x 8 experts each
    for (int e = warp * 8; e < warp * 8 + 8; e++) {
        const float* wrow = gw + (size_t)e * H;
        float s = 0.f;
        for (int h = lane; h < H; h += 32) s = fmaf(xs[h], wrow[h], s);
        #pragma unroll
        for (int o = 16; o; o >>= 1) s += __shfl_xor_sync(0xffffffffu, s, o);
        if (lane == 0) logits[e] = s;
    }
    __syncthreads();

    if (warp == 0) {
        float l0 = logits[lane], l1 = logits[lane + 32];
        int   sel_i[TOPK];
        float sel_v[TOPK];
        #pragma unroll
        for (int k = 0; k < TOPK; k++) {
            float v; int idx;
            if (l0 >= l1) { v = l0; idx = lane; } else { v = l1; idx = lane + 32; }
            #pragma unroll
            for (int o = 16; o; o >>= 1) {
                float ov = __shfl_xor_sync(0xffffffffu, v, o);
                int   oi = __shfl_xor_sync(0xffffffffu, idx, o);
                if (ov > v || (ov == v && oi < idx)) { v = ov; idx = oi; }
            }
            sel_i[k] = idx; sel_v[k] = v;
            if (idx == lane) l0 = -CUDART_INF_F;
            else if (idx == lane + 32) l1 = -CUDART_INF_F;
        }
        if (lane == 0) {
            float m = sel_v[0];  // largest
            float ww[TOPK], s = 0.f;
            #pragma unroll
            for (int k = 0; k < TOPK; k++) { ww[k] = __expf(sel_v[k] - m); s += ww[k]; }
            float inv = 1.f / s;
            #pragma unroll
            for (int k = 0; k < TOPK; k++) {
                g_topk_idx[t * TOPK + k] = sel_i[k];
                g_topk_w[t * TOPK + k] = ww[k] * inv;
                atomicAdd(&g_counts[sel_i[k]], 1);
            }
        }
    }
}

// ---------------- scan: offsets ----------------------------------------------
__global__ void scan_kernel() {
    if (threadIdx.x == 0) {
        int acc = 0;
        for (int e = 0; e < E; e++) { g_offsets[e] = acc; acc += g_counts[e]; }
        g_offsets[E] = acc;  // == NSLOT
    }
}

// ---------------- scatter tokens into per-expert slot lists -------------------
__global__ void scatter_kernel() {
    int i = blockIdx.x * blockDim.x + threadIdx.x;
    if (i >= NSLOT) return;
    int t = i / TOPK;
    int e = g_topk_idx[i];
    int pos = g_offsets[e] + atomicAdd(&g_fill[e], 1);
    g_slot_token[pos] = t;
    g_slot_w[pos] = g_topk_w[i];
}

// ---------------- tiled GEMM: 128x128x16, 8x8 per thread ----------------------
// MODE 0: C[slot, :ND] = X[gather(slot), :KD] @ W_e            (stage A)
// MODE 1: out[token(slot), :ND] += w(slot) * A[slot] @ W_e     (stage B, atomic)
template <int KD, int ND, int MODE>
__global__ __launch_bounds__(256) void gemm_kernel(const float* __restrict__ A,
                                                   const float* __restrict__ W,
                                                   float* __restrict__ C) {
    constexpr int TM = 128, TN = 128, TK = 16;
    __shared__ float As[TK][TM + 4];
    __shared__ float Bs[TK][TN];

    int e = blockIdx.y;
    int rbeg = g_offsets[e], rend = g_offsets[e + 1];
    int m0 = rbeg + blockIdx.z * TM;
    if (m0 >= rend) return;
    int n0 = blockIdx.x * TN;
    const float* We = W + (size_t)e * KD * ND;

    int tid = threadIdx.x;
    int tx = tid & 15, ty = tid >> 4;

    float acc[8][8];
    #pragma unroll
    for (int i = 0; i < 8; i++)
        #pragma unroll
        for (int j = 0; j < 8; j++) acc[i][j] = 0.f;

    // precompute per-fragment A source pointers (row gather resolved once)
    const float* aptr[2];
    #pragma unroll
    for (int p = 0; p < 2; p++) {
        int fid = tid + p * 256;      // 0..511
        int r = fid >> 2;             // 0..127
        int row = m0 + r;
        if (row < rend) {
            int src = (MODE == 0) ? g_slot_token[row] : row;
            aptr[p] = A + (size_t)src * KD + (fid & 3) * 4;
        } else {
            aptr[p] = nullptr;
        }
    }

    for (int k0 = 0; k0 < KD; k0 += TK) {
        #pragma unroll
        for (int p = 0; p < 2; p++) {
            int fid = tid + p * 256;
            int r = fid >> 2;
            int kq = (fid & 3) * 4;
            float4 v = make_float4(0.f, 0.f, 0.f, 0.f);
            if (aptr[p]) v = *(const float4*)(aptr[p] + k0);
            As[kq + 0][r] = v.x; As[kq + 1][r] = v.y;
            As[kq + 2][r] = v.z; As[kq + 3][r] = v.w;
        }
        #pragma unroll
        for (int p = 0; p < 2; p++) {
            int fid = tid + p * 256;
            int k = fid >> 5;
            int n4 = (fid & 31) * 4;
            *(float4*)&Bs[k][n4] = *(const float4*)(We + (size_t)(k0 + k) * ND + n0 + n4);
        }
        __syncthreads();

        #pragma unroll
        for (int kk = 0; kk < TK; kk++) {
            float a[8], b[8];
            *(float4*)&a[0] = *(const float4*)&As[kk][ty * 8];
            *(float4*)&a[4] = *(const float4*)&As[kk][ty * 8 + 4];
            *(float4*)&b[0] = *(const float4*)&Bs[kk][tx * 8];
            *(float4*)&b[4] = *(const float4*)&Bs[kk][tx * 8 + 4];
            #pragma unroll
            for (int i = 0; i < 8; i++)
                #pragma unroll
                for (int j = 0; j < 8; j++)
                    acc[i][j] = fmaf(a[i], b[j], acc[i][j]);
        }
        __syncthreads();
    }

    #pragma unroll
    for (int i = 0; i < 8; i++) {
        int row = m0 + ty * 8 + i;
        if (row < rend) {
            if (MODE == 0) {
                float* dst = C + (size_t)row * ND + n0 + tx * 8;
                float4 v0 = make_float4(acc[i][0], acc[i][1], acc[i][2], acc[i][3]);
                float4 v1 = make_float4(acc[i][4], acc[i][5], acc[i][6], acc[i][7]);
                *(float4*)(dst) = v0;
                *(float4*)(dst + 4) = v1;
            } else {
                int tok = g_slot_token[row];
                float gwt = g_slot_w[row];
                float* dst = C + (size_t)tok * ND + n0 + tx * 8;
                #pragma unroll
                for (int j = 0; j < 8; j++) atomicAdd(dst + j, gwt * acc[i][j]);
            }
        }
    }
}

// ---------------- SwiGLU elementwise ------------------------------------------
__global__ void silu_mul_kernel() {
    size_t n = (size_t)NSLOT * I;
    size_t i = (size_t)blockIdx.x * blockDim.x + threadIdx.x;
    size_t stride = (size_t)gridDim.x * blockDim.x;
    for (; i < n; i += stride) {
        float g = g_gbuf[i];
        float u = g_ubuf[i];
        g_gbuf[i] = (g / (1.f + __expf(-g))) * u;
    }
}

// ---------------- zero output -------------------------------------------------
__global__ void zero_kernel(float* __restrict__ out, int n4) {
    int i = blockIdx.x * blockDim.x + threadIdx.x;
    if (i < n4) ((float4*)out)[i] = make_float4(0.f, 0.f, 0.f, 0.f);
}

// ---------------- launch ------------------------------------------------------
extern "C" void kernel_launch(void* const* d_in, const int* in_sizes, int n_in,
                              void* d_out, int out_size) {
    const float* x    = (const float*)d_in[0];  // [1,1024,2048]
    const float* gw   = (const float*)d_in[1];  // [64,2048]
    const float* w1   = (const float*)d_in[2];  // [64,2048,768]
    const float* w3   = (const float*)d_in[3];  // [64,2048,768]
    const float* w2   = (const float*)d_in[4];  // [64,768,2048]
    float* out = (float*)d_out;                 // [1,1024,2048]

    float* gbuf; cudaGetSymbolAddress((void**)&gbuf, g_gbuf);
    float* ubuf; cudaGetSymbolAddress((void**)&ubuf, g_ubuf);

    init_kernel<<<1, 64>>>();
    gate_kernel<<<T, 256>>>(x, gw);
    scan_kernel<<<1, 32>>>();
    scatter_kernel<<<(NSLOT + 255) / 256, 256>>>();

    // stage A: g = X@w1, u = X@w3  (grid: n-tiles x experts x m-tiles, early exit)
    dim3 gridA(I / 128, E, T / 128);
    gemm_kernel<H, I, 0><<<gridA, 256>>>(x, w1, gbuf);
    gemm_kernel<H, I, 0><<<gridA, 256>>>(x, w3, ubuf);

    silu_mul_kernel<<<4096, 256>>>();

    zero_kernel<<<(out_size / 4 + 255) / 256, 256>>>(out, out_size / 4);

    // stage B: out[token] += w * act @ w2
    dim3 gridB(H / 128, E, T / 128);
    gemm_kernel<I, H, 1><<<gridB, 256>>>(gbuf, w2, out);
}

// round 3
// speedup vs baseline: 3.4954x; 3.4954x over previous
#include <cuda_runtime.h>
#include <math.h>
#include <math_constants.h>
#include <cstdint>

// Problem constants (Qwen3 MoE block: B=1, S=1024, H=2048, E=64, I=768, top_k=8)
constexpr int T = 1024;
constexpr int H = 2048;
constexpr int E = 64;
constexpr int I = 768;
constexpr int TOPK = 8;
constexpr int NSLOT = T * TOPK;  // 8192

// ---------------- scratch (device globals) ------------------------------------
__device__ int   g_topk_idx[NSLOT];
__device__ float g_topk_w[NSLOT];
__device__ int   g_counts[E];
__device__ int   g_offsets[E + 1];
__device__ int   g_fill[E];
__device__ int   g_slot_token[NSLOT];  // slot -> token
__device__ int   g_slot_of[NSLOT];     // (t,k) -> slot
__device__ float g_gbuf[(size_t)NSLOT * I];   // g, then act
__device__ float g_ybuf[(size_t)NSLOT * H];

// ---------------- PTX helpers -------------------------------------------------
__device__ __forceinline__ uint32_t smem_u32(const void* p) {
    uint32_t a;
    asm("{ .reg .u64 t; cvta.to.shared.u64 t, %1; cvt.u32.u64 %0, t; }" : "=r"(a) : "l"(p));
    return a;
}
__device__ __forceinline__ uint32_t f2tf(float x) {
    uint32_t r; asm("cvt.rna.tf32.f32 %0, %1;" : "=r"(r) : "f"(x)); return r;
}
__device__ __forceinline__ void cpa16(uint32_t dst, const void* src, int sz) {
    asm volatile("cp.async.cg.shared.global [%0], [%1], 16, %2;"
                 :: "r"(dst), "l"(src), "r"(sz) : "memory");
}
#define CP_COMMIT() asm volatile("cp.async.commit_group;" ::: "memory")
#define CP_WAIT(n)  asm volatile("cp.async.wait_group %0;" :: "n"(n) : "memory")

__device__ __forceinline__ void mma_tf32(float& d0, float& d1, float& d2, float& d3,
                                         const uint32_t* a, const uint32_t* b) {
    asm volatile(
        "mma.sync.aligned.m16n8k8.row.col.f32.tf32.tf32.f32 "
        "{%0,%1,%2,%3}, {%4,%5,%6,%7}, {%8,%9}, {%0,%1,%2,%3};"
        : "+f"(d0), "+f"(d1), "+f"(d2), "+f"(d3)
        : "r"(a[0]), "r"(a[1]), "r"(a[2]), "r"(a[3]), "r"(b[0]), "r"(b[1]));
}

// ---------------- init --------------------------------------------------------
__global__ void init_kernel() {
    int i = threadIdx.x;
    if (i < E) { g_counts[i] = 0; g_fill[i] = 0; }
}

// ---------------- gating ------------------------------------------------------
__global__ __launch_bounds__(256) void gate_kernel(const float* __restrict__ x,
                                                   const float* __restrict__ gw) {
    __shared__ float xs[H];
    __shared__ float logits[E];
    int t = blockIdx.x;
    const float* xr = x + (size_t)t * H;
    for (int i = threadIdx.x; i < H; i += 256) xs[i] = xr[i];
    __syncthreads();

    int warp = threadIdx.x >> 5, lane = threadIdx.x & 31;
    for (int e = warp * 8; e < warp * 8 + 8; e++) {
        const float* wrow = gw + (size_t)e * H;
        float s = 0.f;
        for (int h = lane; h < H; h += 32) s = fmaf(xs[h], wrow[h], s);
        #pragma unroll
        for (int o = 16; o; o >>= 1) s += __shfl_xor_sync(0xffffffffu, s, o);
        if (lane == 0) logits[e] = s;
    }
    __syncthreads();

    if (warp == 0) {
        float l0 = logits[lane], l1 = logits[lane + 32];
        int sel_i[TOPK]; float sel_v[TOPK];
        #pragma unroll
        for (int k = 0; k < TOPK; k++) {
            float v; int idx;
            if (l0 >= l1) { v = l0; idx = lane; } else { v = l1; idx = lane + 32; }
            #pragma unroll
            for (int o = 16; o; o >>= 1) {
                float ov = __shfl_xor_sync(0xffffffffu, v, o);
                int   oi = __shfl_xor_sync(0xffffffffu, idx, o);
                if (ov > v || (ov == v && oi < idx)) { v = ov; idx = oi; }
            }
            sel_i[k] = idx; sel_v[k] = v;
            if (idx == lane) l0 = -CUDART_INF_F;
            else if (idx == lane + 32) l1 = -CUDART_INF_F;
        }
        if (lane == 0) {
            float m = sel_v[0];
            float ww[TOPK], s = 0.f;
            #pragma unroll
            for (int k = 0; k < TOPK; k++) { ww[k] = __expf(sel_v[k] - m); s += ww[k]; }
            float inv = 1.f / s;
            #pragma unroll
            for (int k = 0; k < TOPK; k++) {
                g_topk_idx[t * TOPK + k] = sel_i[k];
                g_topk_w[t * TOPK + k] = ww[k] * inv;
                atomicAdd(&g_counts[sel_i[k]], 1);
            }
        }
    }
}

__global__ void scan_kernel() {
    if (threadIdx.x == 0) {
        int acc = 0;
        for (int e = 0; e < E; e++) { g_offsets[e] = acc; acc += g_counts[e]; }
        g_offsets[E] = acc;
    }
}

__global__ void scatter_kernel() {
    int i = blockIdx.x * blockDim.x + threadIdx.x;
    if (i >= NSLOT) return;
    int t = i / TOPK;
    int e = g_topk_idx[i];
    int pos = g_offsets[e] + atomicAdd(&g_fill[e], 1);
    g_slot_token[pos] = t;
    g_slot_of[i] = pos;
}

// ---------------- tf32 mma.sync grouped GEMM ----------------------------------
// CTA tile: M=128 x N=128, K-chunk 32. 8 warps as 4(m) x 2(n); warp tile 32x64.
// 3-stage cp.async pipeline. A rows gathered per-expert slot list.
// EPI=0: C[row] = result.   EPI=1: C[row] = silu(C_prev[row]) * result (SwiGLU).
constexpr int AST = 36;                 // A smem row stride (floats): banks m*4+k
constexpr int BST = 136;                // B smem row stride (floats): banks k*8+n
constexpr int ASZ = 128 * AST;          // floats per A stage
constexpr int BSZ = 32 * BST;           // floats per B stage
constexpr int STAGES = 3;
constexpr int SMEM_BYTES = STAGES * (ASZ + BSZ) * 4;  // 107520

template <int KD, int ND, int GATHER, int EPI>
__global__ __launch_bounds__(256, 2) void mma_gemm(const float* __restrict__ A,
                                                   const float* __restrict__ W,
                                                   float* __restrict__ C) {
    extern __shared__ float sm[];
    float* Asm = sm;
    float* Bsm = sm + STAGES * ASZ;

    const int e = blockIdx.y;
    const int rbeg = g_offsets[e], rend = g_offsets[e + 1];
    const int m0 = rbeg + blockIdx.z * 128;
    if (m0 >= rend) return;
    const int n0 = blockIdx.x * 128;

    const int tid = threadIdx.x, wid = tid >> 5, lane = tid & 31;
    const int gq = lane >> 2, tg = lane & 3;
    const int mw = (wid & 3) * 32, nw = (wid >> 2) * 64;

    // --- staging coordinates ---
    const int ar = tid >> 1, ah = tid & 1;         // A: 2 threads/row
    const int arow = m0 + ar;
    const bool aok = arow < rend;
    const int asrc = aok ? (GATHER ? g_slot_token[arow] : arow) : 0;
    const float* aG = A + (size_t)asrc * KD + ah * 16;
    const int asz = aok ? 16 : 0;
    const uint32_t aS = smem_u32(Asm) + (uint32_t)(ar * AST + ah * 16) * 4;

    const int bk = tid >> 3, bh = tid & 7;         // B: 8 threads/row(k)
    const float* bG = W + (size_t)e * KD * ND + (size_t)bk * ND + n0 + bh * 16;
    const uint32_t bS = smem_u32(Bsm) + (uint32_t)(bk * BST + bh * 16) * 4;

    const int nch = KD / 32;

    auto load_stage = [&](int ci, int s) {
        const float* ag = aG + ci * 32;
        const float* bg = bG + (size_t)ci * 32 * ND;
        uint32_t as_ = aS + (uint32_t)(s * ASZ) * 4;
        uint32_t bs_ = bS + (uint32_t)(s * BSZ) * 4;
        #pragma unroll
        for (int j = 0; j < 4; j++) cpa16(as_ + j * 16, ag + j * 4, asz);
        #pragma unroll
        for (int j = 0; j < 4; j++) cpa16(bs_ + j * 16, bg + j * 4, 16);
        CP_COMMIT();
    };

    float acc[2][8][4];
    #pragma unroll
    for (int mf = 0; mf < 2; mf++)
        #pragma unroll
        for (int nf = 0; nf < 8; nf++)
            #pragma unroll
            for (int q = 0; q < 4; q++) acc[mf][nf][q] = 0.f;

    load_stage(0, 0);
    if (nch > 1) load_stage(1, 1);

    int s = 0;
    for (int ci = 0; ci < nch; ci++) {
        if (ci + 1 < nch) { CP_WAIT(1); } else { CP_WAIT(0); }
        __syncthreads();

        const float* As = Asm + s * ASZ;
        const float* Bs = Bsm + s * BSZ;
        #pragma unroll
        for (int k8 = 0; k8 < 4; k8++) {
            const int kb = k8 * 8;
            uint32_t aF[2][4];
            #pragma unroll
            for (int mf = 0; mf < 2; mf++) {
                const float* ap = As + (mw + mf * 16 + gq) * AST + kb + tg;
                aF[mf][0] = f2tf(ap[0]);
                aF[mf][1] = f2tf(ap[8 * AST]);
                aF[mf][2] = f2tf(ap[4]);
                aF[mf][3] = f2tf(ap[8 * AST + 4]);
            }
            uint32_t bF[8][2];
            #pragma unroll
            for (int nf = 0; nf < 8; nf++) {
                const float* bp = Bs + (kb + tg) * BST + nw + nf * 8 + gq;
                bF[nf][0] = f2tf(bp[0]);
                bF[nf][1] = f2tf(bp[4 * BST]);
            }
            #pragma unroll
            for (int mf = 0; mf < 2; mf++)
                #pragma unroll
                for (int nf = 0; nf < 8; nf++)
                    mma_tf32(acc[mf][nf][0], acc[mf][nf][1], acc[mf][nf][2],
                             acc[mf][nf][3], aF[mf], bF[nf]);
        }
        __syncthreads();
        if (ci + 2 < nch) load_stage(ci + 2, (ci + 2) % STAGES);
        s = (s + 1 == STAGES) ? 0 : s + 1;
    }

    // --- epilogue ---
    #pragma unroll
    for (int mf = 0; mf < 2; mf++) {
        #pragma unroll
        for (int hr = 0; hr < 2; hr++) {
            const int row = m0 + mw + mf * 16 + gq + hr * 8;
            if (row < rend) {
                float* cr = C + (size_t)row * ND + n0 + nw;
                #pragma unroll
                for (int nf = 0; nf < 8; nf++) {
                    const int col = nf * 8 + 2 * tg;
                    float v0 = acc[mf][nf][hr * 2 + 0];
                    float v1 = acc[mf][nf][hr * 2 + 1];
                    if (EPI == 1) {
                        float2 gv = *(float2*)(cr + col);
                        v0 *= gv.x / (1.f + __expf(-gv.x));
                        v1 *= gv.y / (1.f + __expf(-gv.y));
                    }
                    *(float2*)(cr + col) = make_float2(v0, v1);
                }
            }
        }
    }
}

// ---------------- combine: out[t] = sum_k w[t,k] * ybuf[slot_of[t,k]] ----------
__global__ __launch_bounds__(256) void combine_kernel(float* __restrict__ out) {
    const int t = blockIdx.x;
    __shared__ float w[TOPK];
    __shared__ int rowi[TOPK];
    if (threadIdx.x < TOPK) {
        w[threadIdx.x] = g_topk_w[t * TOPK + threadIdx.x];
        rowi[threadIdx.x] = g_slot_of[t * TOPK + threadIdx.x];
    }
    __syncthreads();
    float4* orow = (float4*)(out + (size_t)t * H);
    for (int j = threadIdx.x; j < H / 4; j += 256) {
        float4 acc = make_float4(0.f, 0.f, 0.f, 0.f);
        #pragma unroll
        for (int k = 0; k < TOPK; k++) {
            const float4 v = ((const float4*)(g_ybuf + (size_t)rowi[k] * H))[j];
            acc.x = fmaf(w[k], v.x, acc.x);
            acc.y = fmaf(w[k], v.y, acc.y);
            acc.z = fmaf(w[k], v.z, acc.z);
            acc.w = fmaf(w[k], v.w, acc.w);
        }
        orow[j] = acc;
    }
}

// ---------------- launch ------------------------------------------------------
extern "C" void kernel_launch(void* const* d_in, const int* in_sizes, int n_in,
                              void* d_out, int out_size) {
    const float* x  = (const float*)d_in[0];  // [1,1024,2048]
    const float* gw = (const float*)d_in[1];  // [64,2048]
    const float* w1 = (const float*)d_in[2];  // [64,2048,768]
    const float* w3 = (const float*)d_in[3];  // [64,2048,768]
    const float* w2 = (const float*)d_in[4];  // [64,768,2048]
    float* out = (float*)d_out;               // [1,1024,2048]

    float* gbuf; cudaGetSymbolAddress((void**)&gbuf, g_gbuf);
    float* ybuf; cudaGetSymbolAddress((void**)&ybuf, g_ybuf);

    cudaFuncSetAttribute(mma_gemm<H, I, 1, 0>, cudaFuncAttributeMaxDynamicSharedMemorySize, SMEM_BYTES);
    cudaFuncSetAttribute(mma_gemm<H, I, 1, 1>, cudaFuncAttributeMaxDynamicSharedMemorySize, SMEM_BYTES);
    cudaFuncSetAttribute(mma_gemm<I, H, 0, 0>, cudaFuncAttributeMaxDynamicSharedMemorySize, SMEM_BYTES);

    init_kernel<<<1, 64>>>();
    gate_kernel<<<T, 256>>>(x, gw);
    scan_kernel<<<1, 32>>>();
    scatter_kernel<<<(NSLOT + 255) / 256, 256>>>();

    // stage A: g = X@w1 (plain); then act = silu(g) * (X@w3) fused in epilogue
    dim3 gridA(I / 128, E, T / 128);
    mma_gemm<H, I, 1, 0><<<gridA, 256, SMEM_BYTES>>>(x, w1, gbuf);
    mma_gemm<H, I, 1, 1><<<gridA, 256, SMEM_BYTES>>>(x, w3, gbuf);

    // stage B: ybuf = act @ w2
    dim3 gridB(H / 128, E, T / 128);
    mma_gemm<I, H, 0, 0><<<gridB, 256, SMEM_BYTES>>>(gbuf, w2, ybuf);

    combine_kernel<<<T, 256>>>(out);
}

// round 6
// speedup vs baseline: 4.1328x; 1.1824x over previous
#include <cuda_runtime.h>
#include <cuda_fp16.h>
#include <math.h>
#include <math_constants.h>
#include <cstdint>

// Problem constants (Qwen3 MoE: B=1, S=1024, H=2048, E=64, I=768, top_k=8)
constexpr int T = 1024;
constexpr int H = 2048;
constexpr int E = 64;
constexpr int I = 768;
constexpr int TOPK = 8;
constexpr int NSLOT = T * TOPK;  // 8192

// ---------------- scratch (device globals) ------------------------------------
__device__ int   g_topk_idx[NSLOT];
__device__ float g_topk_w[NSLOT];
__device__ int   g_counts[E];
__device__ int   g_offsets[E + 1];
__device__ int   g_fill[E];
__device__ int   g_slot_token[NSLOT];
__device__ int   g_slot_of[NSLOT];
__device__ __align__(16) __half g_xh[(size_t)T * H];
__device__ __align__(16) __half g_w1h[(size_t)E * H * I];
__device__ __align__(16) __half g_w3h[(size_t)E * H * I];
__device__ __align__(16) __half g_w2h[(size_t)E * I * H];
__device__ __align__(16) __half g_gbuf[(size_t)NSLOT * I];   // g, then act (fp16)
__device__ __align__(16) float  g_ybuf[(size_t)NSLOT * H];

// ---------------- PTX helpers -------------------------------------------------
__device__ __forceinline__ uint32_t smem_u32(const void* p) {
    uint32_t a;
    asm("{ .reg .u64 t; cvta.to.shared.u64 t, %1; cvt.u32.u64 %0, t; }" : "=r"(a) : "l"(p));
    return a;
}
__device__ __forceinline__ uint32_t h2u(__half2 h) {
    union { __half2 h; uint32_t u; } c; c.h = h; return c.u;
}
__device__ __forceinline__ void cpa16(uint32_t dst, const void* src, int sz) {
    asm volatile("cp.async.cg.shared.global [%0], [%1], 16, %2;"
                 :: "r"(dst), "l"(src), "r"(sz) : "memory");
}
#define CP_COMMIT() asm volatile("cp.async.commit_group;" ::: "memory")
#define CP_WAIT(n)  asm volatile("cp.async.wait_group %0;" :: "n"(n) : "memory")

#define LDM_X4(r0, r1, r2, r3, a) \
    asm volatile("ldmatrix.sync.aligned.m8n8.x4.shared.b16 {%0,%1,%2,%3}, [%4];" \
                 : "=r"(r0), "=r"(r1), "=r"(r2), "=r"(r3) : "r"(a))
#define LDM_X4T(r0, r1, r2, r3, a) \
    asm volatile("ldmatrix.sync.aligned.m8n8.x4.trans.shared.b16 {%0,%1,%2,%3}, [%4];" \
                 : "=r"(r0), "=r"(r1), "=r"(r2), "=r"(r3) : "r"(a))

__device__ __forceinline__ void mma16816(float& d0, float& d1, float& d2, float& d3,
                                         uint32_t a0, uint32_t a1, uint32_t a2, uint32_t a3,
                                         uint32_t b0, uint32_t b1) {
    asm volatile(
        "mma.sync.aligned.m16n8k16.row.col.f32.f16.f16.f32 "
        "{%0,%1,%2,%3}, {%4,%5,%6,%7}, {%8,%9}, {%0,%1,%2,%3};"
        : "+f"(d0), "+f"(d1), "+f"(d2), "+f"(d3)
        : "r"(a0), "r"(a1), "r"(a2), "r"(a3), "r"(b0), "r"(b1));
}

// ---------------- init --------------------------------------------------------
__global__ void init_kernel() {
    int i = threadIdx.x;
    if (i < E) { g_counts[i] = 0; g_fill[i] = 0; }
}

// ---------------- fp32 -> fp16 conversion (vectorized) ------------------------
__global__ __launch_bounds__(256) void conv_kernel(const float* __restrict__ in,
                                                   __half* __restrict__ out, int n8) {
    int i = blockIdx.x * blockDim.x + threadIdx.x;
    int stride = gridDim.x * blockDim.x;
    const float4* in4 = (const float4*)in;
    uint4* out8 = (uint4*)out;
    for (; i < n8; i += stride) {
        float4 a = in4[2 * i], b = in4[2 * i + 1];
        uint4 o;
        o.x = h2u(__floats2half2_rn(a.x, a.y));
        o.y = h2u(__floats2half2_rn(a.z, a.w));
        o.z = h2u(__floats2half2_rn(b.x, b.y));
        o.w = h2u(__floats2half2_rn(b.z, b.w));
        out8[i] = o;
    }
}

// ---------------- gating: 4 tokens per block ----------------------------------
__global__ __launch_bounds__(256) void gate_kernel(const float* __restrict__ x,
                                                   const float* __restrict__ gw) {
    __shared__ float xs[4][H];
    __shared__ float logits[4][E];
    const int t0 = blockIdx.x * 4;
    for (int i = threadIdx.x; i < 4 * H; i += 256)
        xs[i >> 11][i & (H - 1)] = x[(size_t)t0 * H + i];
    __syncthreads();

    const int warp = threadIdx.x >> 5, lane = threadIdx.x & 31;
    for (int ee = 0; ee < 8; ee++) {
        const int e = warp * 8 + ee;
        const float* wrow = gw + (size_t)e * H;
        float a0 = 0.f, a1 = 0.f, a2 = 0.f, a3 = 0.f;
        for (int h = lane; h < H; h += 32) {
            float wv = wrow[h];
            a0 = fmaf(wv, xs[0][h], a0);
            a1 = fmaf(wv, xs[1][h], a1);
            a2 = fmaf(wv, xs[2][h], a2);
            a3 = fmaf(wv, xs[3][h], a3);
        }
        #pragma unroll
        for (int o = 16; o; o >>= 1) {
            a0 += __shfl_xor_sync(0xffffffffu, a0, o);
            a1 += __shfl_xor_sync(0xffffffffu, a1, o);
            a2 += __shfl_xor_sync(0xffffffffu, a2, o);
            a3 += __shfl_xor_sync(0xffffffffu, a3, o);
        }
        if (lane == 0) {
            logits[0][e] = a0; logits[1][e] = a1;
            logits[2][e] = a2; logits[3][e] = a3;
        }
    }
    __syncthreads();

    if (warp < 4) {
        const int t = t0 + warp;
        float l0 = logits[warp][lane], l1 = logits[warp][lane + 32];
        int sel_i[TOPK]; float sel_v[TOPK];
        #pragma unroll
        for (int k = 0; k < TOPK; k++) {
            float v; int idx;
            if (l0 >= l1) { v = l0; idx = lane; } else { v = l1; idx = lane + 32; }
            #pragma unroll
            for (int o = 16; o; o >>= 1) {
                float ov = __shfl_xor_sync(0xffffffffu, v, o);
                int   oi = __shfl_xor_sync(0xffffffffu, idx, o);
                if (ov > v || (ov == v && oi < idx)) { v = ov; idx = oi; }
            }
            sel_i[k] = idx; sel_v[k] = v;
            if (idx == lane) l0 = -CUDART_INF_F;
            else if (idx == lane + 32) l1 = -CUDART_INF_F;
        }
        if (lane == 0) {
            float m = sel_v[0];
            float ww[TOPK], s = 0.f;
            #pragma unroll
            for (int k = 0; k < TOPK; k++) { ww[k] = __expf(sel_v[k] - m); s += ww[k]; }
            float inv = 1.f / s;
            #pragma unroll
            for (int k = 0; k < TOPK; k++) {
                g_topk_idx[t * TOPK + k] = sel_i[k];
                g_topk_w[t * TOPK + k] = ww[k] * inv;
                atomicAdd(&g_counts[sel_i[k]], 1);
            }
        }
    }
}

__global__ void scan_kernel() {
    if (threadIdx.x == 0) {
        int acc = 0;
        for (int e = 0; e < E; e++) { g_offsets[e] = acc; acc += g_counts[e]; }
        g_offsets[E] = acc;
    }
}

__global__ void scatter_kernel() {
    int i = blockIdx.x * blockDim.x + threadIdx.x;
    if (i >= NSLOT) return;
    int t = i / TOPK;
    int e = g_topk_idx[i];
    int pos = g_offsets[e] + atomicAdd(&g_fill[e], 1);
    g_slot_token[pos] = t;
    g_slot_of[i] = pos;
}

// ---------------- fp16 mma.sync grouped GEMM ----------------------------------
// CTA tile 64(M) x 128(N), k-chunk 32, 8 warps as 2(m) x 4(n), warp tile 32x32.
// A: [64 rows][32 k] fp16, row stride 40 halves (80B). B: [32 k][128 n], row
// stride 136 halves (272B). Both strides make ldmatrix conflict-free.
// EPI 0: store half2 (g).  EPI 1: act = silu(g_prev)*res, store half2.
// EPI 2: store float2 (ybuf).
constexpr int AROW = 40;    // halves
constexpr int BROW = 136;   // halves
constexpr int ASTG = 64 * AROW;  // halves per A stage
constexpr int BSTG = 32 * BROW;  // halves per B stage
constexpr int STAGES = 3;
constexpr int MTILES = 8;        // max m-tiles of 64 per expert (cap 512 rows)

template <int KD, int ND, int GATHER, int EPI>
__global__ __launch_bounds__(256, 2) void mma_gemm(const __half* __restrict__ A,
                                                   const __half* __restrict__ W,
                                                   void* __restrict__ Cv,
                                                   const __half* __restrict__ Caux) {
    __shared__ __half Asm[STAGES * ASTG];
    __shared__ __half Bsm[STAGES * BSTG];

    const int e = blockIdx.y;
    const int rbeg = g_offsets[e], rend = g_offsets[e + 1];
    const int m0 = rbeg + blockIdx.x * 64;
    if (m0 >= rend) return;
    const int n0 = blockIdx.z * 128;

    const int tid = threadIdx.x, wid = tid >> 5, lane = tid & 31;
    const int gq = lane >> 2, tg = lane & 3;
    const int mw = (wid & 1) * 32, nw = (wid >> 1) * 32;
    const int r8 = lane & 7, sel = lane >> 3;

    // --- staging coordinates ---
    const int ar = tid >> 2, aseg = tid & 3;        // A: 64 rows x 4 x 16B
    const int arow = m0 + ar;
    const bool aok = arow < rend;
    const int asrc = aok ? (GATHER ? g_slot_token[arow] : arow) : 0;
    const __half* aG = A + (size_t)asrc * KD + aseg * 8;
    const int asz = aok ? 16 : 0;
    const uint32_t aS0 = smem_u32(Asm) + (uint32_t)(ar * 80 + aseg * 16);

    const int br = tid >> 3, bseg = tid & 7;        // B: 32 rows x 8 x 32B
    const __half* bG = W + (size_t)e * KD * ND + (size_t)br * ND + n0 + bseg * 16;
    const uint32_t bS0 = smem_u32(Bsm) + (uint32_t)(br * 272 + bseg * 32);

    // ldmatrix fixed offsets
    uint32_t aRow[2], bCol[2];
    #pragma unroll
    for (int mf = 0; mf < 2; mf++)
        aRow[mf] = (uint32_t)((mw + mf * 16 + ((sel & 1) << 3) + r8) * 80);
    #pragma unroll
    for (int nb = 0; nb < 2; nb++)
        bCol[nb] = (uint32_t)((nw + nb * 16 + ((sel >> 1) << 3)) * 2);
    const uint32_t aColOff = (uint32_t)(((sel >> 1) << 3) * 2);
    const uint32_t bRowOff = (uint32_t)((((sel & 1) << 3) + r8) * 272);
    const uint32_t aBase = smem_u32(Asm), bBase = smem_u32(Bsm);

    const int nch = KD / 32;

    auto load_stage = [&](int ci, int s) {
        const __half* ag = aG + ci * 32;
        const __half* bg = bG + (size_t)ci * 32 * ND;
        uint32_t as_ = aS0 + (uint32_t)(s * ASTG * 2);
        uint32_t bs_ = bS0 + (uint32_t)(s * BSTG * 2);
        cpa16(as_, ag, asz);
        cpa16(bs_, bg, 16);
        cpa16(bs_ + 16, bg + 8, 16);
        CP_COMMIT();
    };

    float acc[2][4][4];
    #pragma unroll
    for (int mf = 0; mf < 2; mf++)
        #pragma unroll
        for (int j = 0; j < 4; j++)
            #pragma unroll
            for (int q = 0; q < 4; q++) acc[mf][j][q] = 0.f;

    load_stage(0, 0);
    if (nch > 1) load_stage(1, 1);

    int s = 0;
    for (int ci = 0; ci < nch; ci++) {
        if (ci + 1 < nch) { CP_WAIT(1); } else { CP_WAIT(0); }
        __syncthreads();

        const uint32_t aStg = aBase + (uint32_t)(s * ASTG * 2);
        const uint32_t bStg = bBase + (uint32_t)(s * BSTG * 2);
        #pragma unroll
        for (int k16 = 0; k16 < 2; k16++) {
            const uint32_t kb = k16 * 16;
            uint32_t aF[2][4], bF[2][4];
            #pragma unroll
            for (int mf = 0; mf < 2; mf++)
                LDM_X4(aF[mf][0], aF[mf][1], aF[mf][2], aF[mf][3],
                       aStg + aRow[mf] + kb * 2 + aColOff);
            #pragma unroll
            for (int nb = 0; nb < 2; nb++)
                LDM_X4T(bF[nb][0], bF[nb][1], bF[nb][2], bF[nb][3],
                        bStg + (kb * 272) + bRowOff + bCol[nb]);
            #pragma unroll
            for (int mf = 0; mf < 2; mf++)
                #pragma unroll
                for (int j = 0; j < 4; j++)
                    mma16816(acc[mf][j][0], acc[mf][j][1], acc[mf][j][2], acc[mf][j][3],
                             aF[mf][0], aF[mf][1], aF[mf][2], aF[mf][3],
                             bF[j >> 1][(j & 1) * 2], bF[j >> 1][(j & 1) * 2 + 1]);
        }
        __syncthreads();
        if (ci + 2 < nch) load_stage(ci + 2, (ci + 2) % STAGES);
        s = (s + 1 == STAGES) ? 0 : s + 1;
    }

    // --- epilogue ---
    #pragma unroll
    for (int mf = 0; mf < 2; mf++) {
        #pragma unroll
        for (int hr = 0; hr < 2; hr++) {
            const int row = m0 + mw + mf * 16 + gq + hr * 8;
            if (row >= rend) continue;
            #pragma unroll
            for (int j = 0; j < 4; j++) {
                const int col = n0 + nw + j * 8 + tg * 2;
                float v0 = acc[mf][j][hr * 2 + 0];
                float v1 = acc[mf][j][hr * 2 + 1];
                if (EPI == 0) {
                    __half2* dst = (__half2*)((__half*)Cv + (size_t)row * ND + col);
                    *dst = __floats2half2_rn(v0, v1);
                } else if (EPI == 1) {
                    const __half2 gh = *(const __half2*)(Caux + (size_t)row * ND + col);
                    float2 gf = __half22float2(gh);
                    v0 *= gf.x / (1.f + __expf(-gf.x));
                    v1 *= gf.y / (1.f + __expf(-gf.y));
                    __half2* dst = (__half2*)((__half*)Cv + (size_t)row * ND + col);
                    *dst = __floats2half2_rn(v0, v1);
                } else {
                    float2* dst = (float2*)((float*)Cv + (size_t)row * ND + col);
                    *dst = make_float2(v0, v1);
                }
            }
        }
    }
}

// ---------------- combine: out[t] = sum_k w[t,k] * ybuf[slot_of[t,k]] ----------
__global__ __launch_bounds__(256) void combine_kernel(float* __restrict__ out) {
    const int t = blockIdx.x;
    __shared__ float w[TOPK];
    __shared__ int rowi[TOPK];
    if (threadIdx.x < TOPK) {
        w[threadIdx.x] = g_topk_w[t * TOPK + threadIdx.x];
        rowi[threadIdx.x] = g_slot_of[t * TOPK + threadIdx.x];
    }
    __syncthreads();
    float4* orow = (float4*)(out + (size_t)t * H);
    for (int j = threadIdx.x; j < H / 4; j += 256) {
        float4 acc = make_float4(0.f, 0.f, 0.f, 0.f);
        #pragma unroll
        for (int k = 0; k < TOPK; k++) {
            const float4 v = ((const float4*)(g_ybuf + (size_t)rowi[k] * H))[j];
            acc.x = fmaf(w[k], v.x, acc.x);
            acc.y = fmaf(w[k], v.y, acc.y);
            acc.z = fmaf(w[k], v.z, acc.z);
            acc.w = fmaf(w[k], v.w, acc.w);
        }
        orow[j] = acc;
    }
}

// ---------------- launch ------------------------------------------------------
extern "C" void kernel_launch(void* const* d_in, const int* in_sizes, int n_in,
                              void* d_out, int out_size) {
    const float* x  = (const float*)d_in[0];
    const float* gw = (const float*)d_in[1];
    const float* w1 = (const float*)d_in[2];
    const float* w3 = (const float*)d_in[3];
    const float* w2 = (const float*)d_in[4];
    float* out = (float*)d_out;

    __half *xh, *w1h, *w3h, *w2h, *gbuf;
    float* ybuf;
    cudaGetSymbolAddress((void**)&xh, g_xh);
    cudaGetSymbolAddress((void**)&w1h, g_w1h);
    cudaGetSymbolAddress((void**)&w3h, g_w3h);
    cudaGetSymbolAddress((void**)&w2h, g_w2h);
    cudaGetSymbolAddress((void**)&gbuf, g_gbuf);
    cudaGetSymbolAddress((void**)&ybuf, g_ybuf);

    init_kernel<<<1, 64>>>();
    gate_kernel<<<T / 4, 256>>>(x, gw);
    scan_kernel<<<1, 32>>>();
    scatter_kernel<<<(NSLOT + 255) / 256, 256>>>();

    const int NW = E * H * I;  // elements per w1/w3 (== w2)
    conv_kernel<<<2048, 256>>>(x, xh, T * H / 8);
    conv_kernel<<<8192, 256>>>(w1, w1h, NW / 8);
    conv_kernel<<<8192, 256>>>(w3, w3h, NW / 8);
    conv_kernel<<<8192, 256>>>(w2, w2h, NW / 8);

    // stage A: g = X@w1; act = silu(g) * (X@w3)
    dim3 gridA(MTILES, E, I / 128);
    mma_gemm<H, I, 1, 0><<<gridA, 256>>>(xh, w1h, gbuf, nullptr);
    mma_gemm<H, I, 1, 1><<<gridA, 256>>>(xh, w3h, gbuf, gbuf);

    // stage B: ybuf = act @ w2
    dim3 gridB(MTILES, E, H / 128);
    mma_gemm<I, H, 0, 2><<<gridB, 256>>>(gbuf, w2h, ybuf, nullptr);

    combine_kernel<<<T, 256>>>(out);
}

// round 7
// speedup vs baseline: 5.4698x; 1.3235x over previous
#include <cuda_runtime.h>
#include <cuda_fp16.h>
#include <math.h>
#include <math_constants.h>
#include <cstdint>

// Problem constants (Qwen3 MoE: B=1, S=1024, H=2048, E=64, I=768, top_k=8)
constexpr int T = 1024;
constexpr int H = 2048;
constexpr int E = 64;
constexpr int I = 768;
constexpr int TOPK = 8;
constexpr int NSLOT = T * TOPK;  // 8192
constexpr int MTILES = 8;        // up to 512 rows per expert

// ---------------- scratch (device globals) ------------------------------------
__device__ int   g_topk_idx[NSLOT];
__device__ float g_topk_w[NSLOT];
__device__ int   g_counts[E];
__device__ int   g_offsets[E + 1];
__device__ int   g_fill[E];
__device__ int   g_slot_token[NSLOT];
__device__ int   g_slot_of[NSLOT];
__device__ __align__(16) __half g_xh[(size_t)T * H];
__device__ __align__(16) __half g_abuf[(size_t)NSLOT * I];   // act (fp16)
__device__ __align__(16) __half g_ybuf[(size_t)NSLOT * H];   // y per slot (fp16)

// ---------------- PTX helpers -------------------------------------------------
__device__ __forceinline__ uint32_t smem_u32(const void* p) {
    uint32_t a;
    asm("{ .reg .u64 t; cvta.to.shared.u64 t, %1; cvt.u32.u64 %0, t; }" : "=r"(a) : "l"(p));
    return a;
}
__device__ __forceinline__ uint32_t h2u(__half2 h) {
    union { __half2 h; uint32_t u; } c; c.h = h; return c.u;
}
__device__ __forceinline__ void cpa16(uint32_t dst, const void* src, int sz) {
    asm volatile("cp.async.cg.shared.global [%0], [%1], 16, %2;"
                 :: "r"(dst), "l"(src), "r"(sz) : "memory");
}
#define CP_COMMIT() asm volatile("cp.async.commit_group;" ::: "memory")
#define CP_WAIT(n)  asm volatile("cp.async.wait_group %0;" :: "n"(n) : "memory")

#define LDM_X4(r0, r1, r2, r3, a) \
    asm volatile("ldmatrix.sync.aligned.m8n8.x4.shared.b16 {%0,%1,%2,%3}, [%4];" \
                 : "=r"(r0), "=r"(r1), "=r"(r2), "=r"(r3) : "r"(a))
#define LDM_X4T(r0, r1, r2, r3, a) \
    asm volatile("ldmatrix.sync.aligned.m8n8.x4.trans.shared.b16 {%0,%1,%2,%3}, [%4];" \
                 : "=r"(r0), "=r"(r1), "=r"(r2), "=r"(r3) : "r"(a))

#define STS32(a, r0, r1) \
    asm volatile("st.shared.v2.b32 [%0], {%1,%2};" :: "r"(a), "r"(r0), "r"(r1) : "memory")

__device__ __forceinline__ void mma16816(float& d0, float& d1, float& d2, float& d3,
                                         uint32_t a0, uint32_t a1, uint32_t a2, uint32_t a3,
                                         uint32_t b0, uint32_t b1) {
    asm volatile(
        "mma.sync.aligned.m16n8k16.row.col.f32.f16.f16.f32 "
        "{%0,%1,%2,%3}, {%4,%5,%6,%7}, {%8,%9}, {%0,%1,%2,%3};"
        : "+f"(d0), "+f"(d1), "+f"(d2), "+f"(d3)
        : "r"(a0), "r"(a1), "r"(a2), "r"(a3), "r"(b0), "r"(b1));
}

// ---------------- init --------------------------------------------------------
__global__ void init_kernel() {
    int i = threadIdx.x;
    if (i < E) { g_counts[i] = 0; g_fill[i] = 0; }
}

// ---------------- fp32 -> fp16 conversion (x only) -----------------------------
__global__ __launch_bounds__(256) void conv_kernel(const float* __restrict__ in,
                                                   __half* __restrict__ out, int n8) {
    int i = blockIdx.x * blockDim.x + threadIdx.x;
    int stride = gridDim.x * blockDim.x;
    const float4* in4 = (const float4*)in;
    uint4* out8 = (uint4*)out;
    for (; i < n8; i += stride) {
        float4 a = in4[2 * i], b = in4[2 * i + 1];
        uint4 o;
        o.x = h2u(__floats2half2_rn(a.x, a.y));
        o.y = h2u(__floats2half2_rn(a.z, a.w));
        o.z = h2u(__floats2half2_rn(b.x, b.y));
        o.w = h2u(__floats2half2_rn(b.z, b.w));
        out8[i] = o;
    }
}

// ---------------- gating: 4 tokens per block ----------------------------------
__global__ __launch_bounds__(256) void gate_kernel(const float* __restrict__ x,
                                                   const float* __restrict__ gw) {
    __shared__ float xs[4][H];
    __shared__ float logits[4][E];
    const int t0 = blockIdx.x * 4;
    for (int i = threadIdx.x; i < 4 * H; i += 256)
        xs[i >> 11][i & (H - 1)] = x[(size_t)t0 * H + i];
    __syncthreads();

    const int warp = threadIdx.x >> 5, lane = threadIdx.x & 31;
    for (int ee = 0; ee < 8; ee++) {
        const int e = warp * 8 + ee;
        const float* wrow = gw + (size_t)e * H;
        float a0 = 0.f, a1 = 0.f, a2 = 0.f, a3 = 0.f;
        for (int h = lane; h < H; h += 32) {
            float wv = wrow[h];
            a0 = fmaf(wv, xs[0][h], a0);
            a1 = fmaf(wv, xs[1][h], a1);
            a2 = fmaf(wv, xs[2][h], a2);
            a3 = fmaf(wv, xs[3][h], a3);
        }
        #pragma unroll
        for (int o = 16; o; o >>= 1) {
            a0 += __shfl_xor_sync(0xffffffffu, a0, o);
            a1 += __shfl_xor_sync(0xffffffffu, a1, o);
            a2 += __shfl_xor_sync(0xffffffffu, a2, o);
            a3 += __shfl_xor_sync(0xffffffffu, a3, o);
        }
        if (lane == 0) {
            logits[0][e] = a0; logits[1][e] = a1;
            logits[2][e] = a2; logits[3][e] = a3;
        }
    }
    __syncthreads();

    if (warp < 4) {
        const int t = t0 + warp;
        float l0 = logits[warp][lane], l1 = logits[warp][lane + 32];
        int sel_i[TOPK]; float sel_v[TOPK];
        #pragma unroll
        for (int k = 0; k < TOPK; k++) {
            float v; int idx;
            if (l0 >= l1) { v = l0; idx = lane; } else { v = l1; idx = lane + 32; }
            #pragma unroll
            for (int o = 16; o; o >>= 1) {
                float ov = __shfl_xor_sync(0xffffffffu, v, o);
                int   oi = __shfl_xor_sync(0xffffffffu, idx, o);
                if (ov > v || (ov == v && oi < idx)) { v = ov; idx = oi; }
            }
            sel_i[k] = idx; sel_v[k] = v;
            if (idx == lane) l0 = -CUDART_INF_F;
            else if (idx == lane + 32) l1 = -CUDART_INF_F;
        }
        if (lane == 0) {
            float m = sel_v[0];
            float ww[TOPK], s = 0.f;
            #pragma unroll
            for (int k = 0; k < TOPK; k++) { ww[k] = __expf(sel_v[k] - m); s += ww[k]; }
            float inv = 1.f / s;
            #pragma unroll
            for (int k = 0; k < TOPK; k++) {
                g_topk_idx[t * TOPK + k] = sel_i[k];
                g_topk_w[t * TOPK + k] = ww[k] * inv;
                atomicAdd(&g_counts[sel_i[k]], 1);
            }
        }
    }
}

__global__ void scan_kernel() {
    if (threadIdx.x == 0) {
        int acc = 0;
        for (int e = 0; e < E; e++) { g_offsets[e] = acc; acc += g_counts[e]; }
        g_offsets[E] = acc;
    }
}

__global__ void scatter_kernel() {
    int i = blockIdx.x * blockDim.x + threadIdx.x;
    if (i >= NSLOT) return;
    int t = i / TOPK;
    int e = g_topk_idx[i];
    int pos = g_offsets[e] + atomicAdd(&g_fill[e], 1);
    g_slot_token[pos] = t;
    g_slot_of[i] = pos;
}

// =====================  Fused up-proj kernel (w1 & w3 + SwiGLU)  ===============
// CTA tile 64(M) x 64(N) x 2 matrices, k-chunk 32, nch = H/32 = 64.
// 8 warps = 2(m) x 2(n) x 2(matrix); warp tile 32x32.
// A (gathered X, fp16) via cp.async double-buffered; B (w1,w3 fp32) via
// LDG.128 register prefetch -> cvt -> STS fp16 (stride 144B, conflict-free).
// Epilogue: g exchanged via smem, act = silu(g)*u -> abuf (fp16).
constexpr int UP_AROW = 80;      // A row stride bytes (40 halves)
constexpr int UP_ASTG = 64 * UP_AROW;           // 5120 B per A stage
constexpr int UP_BROW = 144;     // B row stride bytes (72 halves)
constexpr int UP_BMAT = 32 * UP_BROW;           // 4608 B per matrix
constexpr int UP_BSTG = 2 * UP_BMAT;            // 9216 B per stage

__global__ __launch_bounds__(256, 2) void up_gemm(const __half* __restrict__ X,
                                                  const float* __restrict__ W1,
                                                  const float* __restrict__ W3,
                                                  __half* __restrict__ OUT) {
    __shared__ __align__(16) char smem[2 * UP_ASTG + 2 * UP_BSTG];
    const uint32_t bA = smem_u32(smem);
    const uint32_t bB = bA + 2 * UP_ASTG;

    const int e = blockIdx.y;
    const int rbeg = g_offsets[e], rend = g_offsets[e + 1];
    const int m0 = rbeg + blockIdx.x * 64;
    if (m0 >= rend) return;
    const int n0 = blockIdx.z * 64;

    const int tid = threadIdx.x, wid = tid >> 5, lane = tid & 31;
    const int gq = lane >> 2, tg = lane & 3;
    const int r8 = lane & 7, sel = lane >> 3;
    const int mat = wid >> 2, wm = (wid >> 1) & 1, wn = wid & 1;
    const int mw = wm * 32, nw = wn * 32;

    // --- A staging (fp16 x, gathered) ---
    const int ar = tid >> 2, aseg = tid & 3;
    const int arow = m0 + ar;
    const bool aok = arow < rend;
    const int asrc = aok ? g_slot_token[arow] : 0;
    const __half* aG = X + (size_t)asrc * H + aseg * 8;
    const int asz = aok ? 16 : 0;
    const uint32_t aS0 = bA + (uint32_t)(ar * UP_AROW + aseg * 16);

    // --- B staging (fp32 w1/w3 -> fp16) ---
    const int bmat = tid >> 7;               // 0: w1, 1: w3
    const int brem = tid & 127;
    const int bk = brem >> 2, bseg = brem & 3;   // 32 k-rows x 4 x 16 floats
    const float* bGsrc = (bmat ? W3 : W1) + (size_t)e * H * I +
                         (size_t)bk * I + n0 + bseg * 16;
    const uint32_t bS0 = bB + (uint32_t)(bmat * UP_BMAT + bk * UP_BROW + bseg * 32);

    // --- ldmatrix offsets ---
    uint32_t aRow[2];
    #pragma unroll
    for (int mf = 0; mf < 2; mf++)
        aRow[mf] = (uint32_t)((mw + mf * 16 + ((sel & 1) << 3) + r8) * UP_AROW);
    const uint32_t aColOff = (uint32_t)(((sel >> 1) << 3) * 2);
    uint32_t bCol[2];
    #pragma unroll
    for (int nb = 0; nb < 2; nb++)
        bCol[nb] = (uint32_t)((nw + nb * 16 + ((sel >> 1) << 3)) * 2);
    const uint32_t bRowOff = (uint32_t)((((sel & 1) << 3) + r8) * UP_BROW);
    const uint32_t bMatOff = (uint32_t)(mat * UP_BMAT);

    constexpr int NCH = H / 32;

    float4 b4[4];
    auto ldgB = [&](int ci) {
        const float* p = bGsrc + (size_t)ci * 32 * I;
        #pragma unroll
        for (int j = 0; j < 4; j++) b4[j] = *(const float4*)(p + j * 4);
    };
    auto stsB = [&](int p) {
        const uint32_t d = bS0 + (uint32_t)(p * UP_BSTG);
        #pragma unroll
        for (int j = 0; j < 2; j++) {
            uint32_t h0 = h2u(__floats2half2_rn(b4[2 * j].x, b4[2 * j].y));
            uint32_t h1 = h2u(__floats2half2_rn(b4[2 * j].z, b4[2 * j].w));
            uint32_t h2_ = h2u(__floats2half2_rn(b4[2 * j + 1].x, b4[2 * j + 1].y));
            uint32_t h3 = h2u(__floats2half2_rn(b4[2 * j + 1].z, b4[2 * j + 1].w));
            asm volatile("st.shared.v4.b32 [%0], {%1,%2,%3,%4};"
                         :: "r"(d + j * 16), "r"(h0), "r"(h1), "r"(h2_), "r"(h3) : "memory");
        }
    };
    auto cpaA = [&](int ci) {
        cpa16(aS0 + (uint32_t)((ci & 1) * UP_ASTG), aG + ci * 32, asz);
        CP_COMMIT();
    };

    float acc[2][4][4];
    #pragma unroll
    for (int mf = 0; mf < 2; mf++)
        #pragma unroll
        for (int j = 0; j < 4; j++)
            #pragma unroll
            for (int q = 0; q < 4; q++) acc[mf][j][q] = 0.f;

    ldgB(0);
    cpaA(0);

    int p = 0;
    for (int ci = 0; ci < NCH; ci++) {
        stsB(p);
        if (ci + 1 < NCH) cpaA(ci + 1);
        if (ci + 1 < NCH) { CP_WAIT(1); } else { CP_WAIT(0); }
        __syncthreads();
        if (ci + 1 < NCH) ldgB(ci + 1);

        const uint32_t aStg = bA + (uint32_t)((ci & 1) * UP_ASTG);
        const uint32_t bStg = bB + (uint32_t)(p * UP_BSTG) + bMatOff;
        #pragma unroll
        for (int k16 = 0; k16 < 2; k16++) {
            const uint32_t kb = k16 * 16;
            uint32_t aF[2][4], bF[2][4];
            #pragma unroll
            for (int mf = 0; mf < 2; mf++)
                LDM_X4(aF[mf][0], aF[mf][1], aF[mf][2], aF[mf][3],
                       aStg + aRow[mf] + kb * 2 + aColOff);
            #pragma unroll
            for (int nb = 0; nb < 2; nb++)
                LDM_X4T(bF[nb][0], bF[nb][1], bF[nb][2], bF[nb][3],
                        bStg + kb * UP_BROW + bRowOff + bCol[nb]);
            #pragma unroll
            for (int mf = 0; mf < 2; mf++)
                #pragma unroll
                for (int j = 0; j < 4; j++)
                    mma16816(acc[mf][j][0], acc[mf][j][1], acc[mf][j][2], acc[mf][j][3],
                             aF[mf][0], aF[mf][1], aF[mf][2], aF[mf][3],
                             bF[j >> 1][(j & 1) * 2], bF[j >> 1][(j & 1) * 2 + 1]);
        }
        __syncthreads();
        p ^= 1;
    }

    // --- epilogue: exchange g via smem, act = silu(g) * u ---
    float* exch = (float*)smem;   // 64 x 66 floats = 16896 B (staging dead)
    if (mat == 0) {
        #pragma unroll
        for (int mf = 0; mf < 2; mf++)
            #pragma unroll
            for (int hr = 0; hr < 2; hr++) {
                const int lr = mw + mf * 16 + gq + hr * 8;
                #pragma unroll
                for (int j = 0; j < 4; j++) {
                    const int lc = nw + j * 8 + tg * 2;
                    exch[lr * 66 + lc] = acc[mf][j][hr * 2 + 0];
                    exch[lr * 66 + lc + 1] = acc[mf][j][hr * 2 + 1];
                }
            }
    }
    __syncthreads();
    if (mat == 1) {
        #pragma unroll
        for (int mf = 0; mf < 2; mf++)
            #pragma unroll
            for (int hr = 0; hr < 2; hr++) {
                const int lr = mw + mf * 16 + gq + hr * 8;
                const int row = m0 + lr;
                if (row >= rend) continue;
                #pragma unroll
                for (int j = 0; j < 4; j++) {
                    const int lc = nw + j * 8 + tg * 2;
                    float g0 = exch[lr * 66 + lc];
                    float g1 = exch[lr * 66 + lc + 1];
                    float u0 = acc[mf][j][hr * 2 + 0];
                    float u1 = acc[mf][j][hr * 2 + 1];
                    float v0 = u0 * g0 / (1.f + __expf(-g0));
                    float v1 = u1 * g1 / (1.f + __expf(-g1));
                    __half2* dst = (__half2*)(OUT + (size_t)row * I + n0 + lc);
                    *dst = __floats2half2_rn(v0, v1);
                }
            }
    }
}

// =====================  Down-proj kernel (w2)  =================================
// CTA tile 64(M) x 128(N), k-chunk 32, nch = I/32 = 24. 8 warps = 2m x 4n.
// A = act (fp16, slot rows, no gather) via cp.async; B = w2 fp32 reg-staged.
constexpr int DN_AROW = 80;
constexpr int DN_ASTG = 64 * DN_AROW;   // 5120
constexpr int DN_BROW = 272;            // 128 n + pad, bytes
constexpr int DN_BSTG = 32 * DN_BROW;   // 8704

__global__ __launch_bounds__(256, 2) void down_gemm(const __half* __restrict__ A,
                                                    const float* __restrict__ W2,
                                                    __half* __restrict__ OUT) {
    __shared__ __align__(16) char smem[2 * DN_ASTG + 2 * DN_BSTG];
    const uint32_t bA = smem_u32(smem);
    const uint32_t bB = bA + 2 * DN_ASTG;

    const int e = blockIdx.y;
    const int rbeg = g_offsets[e], rend = g_offsets[e + 1];
    const int m0 = rbeg + blockIdx.x * 64;
    if (m0 >= rend) return;
    const int n0 = blockIdx.z * 128;

    const int tid = threadIdx.x, wid = tid >> 5, lane = tid & 31;
    const int gq = lane >> 2, tg = lane & 3;
    const int r8 = lane & 7, sel = lane >> 3;
    const int mw = (wid & 1) * 32, nw = (wid >> 1) * 32;

    // --- A staging ---
    const int ar = tid >> 2, aseg = tid & 3;
    const int arow = m0 + ar;
    const bool aok = arow < rend;
    const __half* aG = A + (size_t)(aok ? arow : 0) * I + aseg * 8;
    const int asz = aok ? 16 : 0;
    const uint32_t aS0 = bA + (uint32_t)(ar * DN_AROW + aseg * 16);

    // --- B staging: 32 k-rows x 8 x 16 floats ---
    const int bk = tid >> 3, bseg = tid & 7;
    const float* bGsrc = W2 + (size_t)e * I * H + (size_t)bk * H + n0 + bseg * 16;
    const uint32_t bS0 = bB + (uint32_t)(bk * DN_BROW + bseg * 32);

    uint32_t aRow[2];
    #pragma unroll
    for (int mf = 0; mf < 2; mf++)
        aRow[mf] = (uint32_t)((mw + mf * 16 + ((sel & 1) << 3) + r8) * DN_AROW);
    const uint32_t aColOff = (uint32_t)(((sel >> 1) << 3) * 2);
    uint32_t bCol[2];
    #pragma unroll
    for (int nb = 0; nb < 2; nb++)
        bCol[nb] = (uint32_t)((nw + nb * 16 + ((sel >> 1) << 3)) * 2);
    const uint32_t bRowOff = (uint32_t)((((sel & 1) << 3) + r8) * DN_BROW);

    constexpr int NCH = I / 32;

    float4 b4[4];
    auto ldgB = [&](int ci) {
        const float* pp = bGsrc + (size_t)ci * 32 * H;
        #pragma unroll
        for (int j = 0; j < 4; j++) b4[j] = *(const float4*)(pp + j * 4);
    };
    auto stsB = [&](int p) {
        const uint32_t d = bS0 + (uint32_t)(p * DN_BSTG);
        #pragma unroll
        for (int j = 0; j < 2; j++) {
            uint32_t h0 = h2u(__floats2half2_rn(b4[2 * j].x, b4[2 * j].y));
            uint32_t h1 = h2u(__floats2half2_rn(b4[2 * j].z, b4[2 * j].w));
            uint32_t h2_ = h2u(__floats2half2_rn(b4[2 * j + 1].x, b4[2 * j + 1].y));
            uint32_t h3 = h2u(__floats2half2_rn(b4[2 * j + 1].z, b4[2 * j + 1].w));
            asm volatile("st.shared.v4.b32 [%0], {%1,%2,%3,%4};"
                         :: "r"(d + j * 16), "r"(h0), "r"(h1), "r"(h2_), "r"(h3) : "memory");
        }
    };
    auto cpaA = [&](int ci) {
        cpa16(aS0 + (uint32_t)((ci & 1) * DN_ASTG), aG + ci * 32, asz);
        CP_COMMIT();
    };

    float acc[2][4][4];
    #pragma unroll
    for (int mf = 0; mf < 2; mf++)
        #pragma unroll
        for (int j = 0; j < 4; j++)
            #pragma unroll
            for (int q = 0; q < 4; q++) acc[mf][j][q] = 0.f;

    ldgB(0);
    cpaA(0);

    int p = 0;
    for (int ci = 0; ci < NCH; ci++) {
        stsB(p);
        if (ci + 1 < NCH) cpaA(ci + 1);
        if (ci + 1 < NCH) { CP_WAIT(1); } else { CP_WAIT(0); }
        __syncthreads();
        if (ci + 1 < NCH) ldgB(ci + 1);

        const uint32_t aStg = bA + (uint32_t)((ci & 1) * DN_ASTG);
        const uint32_t bStg = bB + (uint32_t)(p * DN_BSTG);
        #pragma unroll
        for (int k16 = 0; k16 < 2; k16++) {
            const uint32_t kb = k16 * 16;
            uint32_t aF[2][4], bF[2][4];
            #pragma unroll
            for (int mf = 0; mf < 2; mf++)
                LDM_X4(aF[mf][0], aF[mf][1], aF[mf][2], aF[mf][3],
                       aStg + aRow[mf] + kb * 2 + aColOff);
            #pragma unroll
            for (int nb = 0; nb < 2; nb++)
                LDM_X4T(bF[nb][0], bF[nb][1], bF[nb][2], bF[nb][3],
                        bStg + kb * DN_BROW + bRowOff + bCol[nb]);
            #pragma unroll
            for (int mf = 0; mf < 2; mf++)
                #pragma unroll
                for (int j = 0; j < 4; j++)
                    mma16816(acc[mf][j][0], acc[mf][j][1], acc[mf][j][2], acc[mf][j][3],
                             aF[mf][0], aF[mf][1], aF[mf][2], aF[mf][3],
                             bF[j >> 1][(j & 1) * 2], bF[j >> 1][(j & 1) * 2 + 1]);
        }
        __syncthreads();
        p ^= 1;
    }

    #pragma unroll
    for (int mf = 0; mf < 2; mf++)
        #pragma unroll
        for (int hr = 0; hr < 2; hr++) {
            const int row = m0 + mw + mf * 16 + gq + hr * 8;
            if (row >= rend) continue;
            #pragma unroll
            for (int j = 0; j < 4; j++) {
                const int col = n0 + nw + j * 8 + tg * 2;
                __half2* dst = (__half2*)(OUT + (size_t)row * H + col);
                *dst = __floats2half2_rn(acc[mf][j][hr * 2 + 0], acc[mf][j][hr * 2 + 1]);
            }
        }
}

// ---------------- combine: out[t] = sum_k w[t,k] * ybuf[slot_of[t,k]] ----------
__global__ __launch_bounds__(256) void combine_kernel(float* __restrict__ out) {
    const int t = blockIdx.x;
    __shared__ float w[TOPK];
    __shared__ int rowi[TOPK];
    if (threadIdx.x < TOPK) {
        w[threadIdx.x] = g_topk_w[t * TOPK + threadIdx.x];
        rowi[threadIdx.x] = g_slot_of[t * TOPK + threadIdx.x];
    }
    __syncthreads();
    const int j = threadIdx.x;  // 256 threads x 8 outputs = 2048 = H
    float acc[8];
    #pragma unroll
    for (int q = 0; q < 8; q++) acc[q] = 0.f;
    #pragma unroll
    for (int k = 0; k < TOPK; k++) {
        const uint4 v = *(const uint4*)(g_ybuf + (size_t)rowi[k] * H + j * 8);
        const __half2* hp = (const __half2*)&v;
        const float wk = w[k];
        #pragma unroll
        for (int q = 0; q < 4; q++) {
            float2 f = __half22float2(hp[q]);
            acc[2 * q + 0] = fmaf(wk, f.x, acc[2 * q + 0]);
            acc[2 * q + 1] = fmaf(wk, f.y, acc[2 * q + 1]);
        }
    }
    float4* orow = (float4*)(out + (size_t)t * H + j * 8);
    orow[0] = make_float4(acc[0], acc[1], acc[2], acc[3]);
    orow[1] = make_float4(acc[4], acc[5], acc[6], acc[7]);
}

// ---------------- launch ------------------------------------------------------
extern "C" void kernel_launch(void* const* d_in, const int* in_sizes, int n_in,
                              void* d_out, int out_size) {
    const float* x  = (const float*)d_in[0];
    const float* gw = (const float*)d_in[1];
    const float* w1 = (const float*)d_in[2];
    const float* w3 = (const float*)d_in[3];
    const float* w2 = (const float*)d_in[4];
    float* out = (float*)d_out;

    __half *xh, *abuf, *ybuf;
    cudaGetSymbolAddress((void**)&xh, g_xh);
    cudaGetSymbolAddress((void**)&abuf, g_abuf);
    cudaGetSymbolAddress((void**)&ybuf, g_ybuf);

    init_kernel<<<1, 64>>>();
    gate_kernel<<<T / 4, 256>>>(x, gw);
    scan_kernel<<<1, 32>>>();
    scatter_kernel<<<(NSLOT + 255) / 256, 256>>>();
    conv_kernel<<<2048, 256>>>(x, xh, T * H / 8);

    // fused up-proj: act = silu(X@w1) * (X@w3)
    dim3 gridU(MTILES, E, I / 64);
    up_gemm<<<gridU, 256>>>(xh, w1, w3, abuf);

    // down-proj: ybuf = act @ w2
    dim3 gridD(MTILES, E, H / 128);
    down_gemm<<<gridD, 256>>>(abuf, w2, ybuf);

    combine_kernel<<<T, 256>>>(out);
}

// round 9
// speedup vs baseline: 6.1743x; 1.1288x over previous
#include <cuda_runtime.h>
#include <cuda_fp16.h>
#include <math.h>
#include <math_constants.h>
#include <cstdint>

// Problem constants (Qwen3 MoE: B=1, S=1024, H=2048, E=64, I=768, top_k=8)
constexpr int T = 1024;
constexpr int H = 2048;
constexpr int E = 64;
constexpr int I = 768;
constexpr int TOPK = 8;
constexpr int NSLOT = T * TOPK;  // 8192

// ---------------- scratch (device globals) ------------------------------------
__device__ int   g_topk_idx[NSLOT];
__device__ float g_topk_w[NSLOT];
__device__ int   g_counts[E];
__device__ int   g_offsets[E + 1];
__device__ int   g_n64[E];      // number of M64 tiles per expert
__device__ int   g_off32[E];    // slot offset of M32 tail tile, or -1
__device__ int   g_fill[E];
__device__ int   g_slot_token[NSLOT];
__device__ int   g_slot_of[NSLOT];
__device__ __align__(16) __half g_xh[(size_t)T * H];
__device__ __align__(16) __half g_abuf[(size_t)NSLOT * I];   // act (fp16)
__device__ __align__(16) __half g_ybuf[(size_t)NSLOT * H];   // y per slot (fp16)

// ---------------- PTX helpers -------------------------------------------------
__device__ __forceinline__ uint32_t smem_u32(const void* p) {
    uint32_t a;
    asm("{ .reg .u64 t; cvta.to.shared.u64 t, %1; cvt.u32.u64 %0, t; }" : "=r"(a) : "l"(p));
    return a;
}
__device__ __forceinline__ uint32_t h2u(__half2 h) {
    union { __half2 h; uint32_t u; } c; c.h = h; return c.u;
}
__device__ __forceinline__ void cpa16(uint32_t dst, const void* src, int sz) {
    asm volatile("cp.async.cg.shared.global [%0], [%1], 16, %2;"
                 :: "r"(dst), "l"(src), "r"(sz) : "memory");
}
#define CP_COMMIT() asm volatile("cp.async.commit_group;" ::: "memory")
#define CP_WAIT(n)  asm volatile("cp.async.wait_group %0;" :: "n"(n) : "memory")

#define LDM_X4(r0, r1, r2, r3, a) \
    asm volatile("ldmatrix.sync.aligned.m8n8.x4.shared.b16 {%0,%1,%2,%3}, [%4];" \
                 : "=r"(r0), "=r"(r1), "=r"(r2), "=r"(r3) : "r"(a))
#define LDM_X4T(r0, r1, r2, r3, a) \
    asm volatile("ldmatrix.sync.aligned.m8n8.x4.trans.shared.b16 {%0,%1,%2,%3}, [%4];" \
                 : "=r"(r0), "=r"(r1), "=r"(r2), "=r"(r3) : "r"(a))

__device__ __forceinline__ void mma16816(float& d0, float& d1, float& d2, float& d3,
                                         uint32_t a0, uint32_t a1, uint32_t a2, uint32_t a3,
                                         uint32_t b0, uint32_t b1) {
    asm volatile(
        "mma.sync.aligned.m16n8k16.row.col.f32.f16.f16.f32 "
        "{%0,%1,%2,%3}, {%4,%5,%6,%7}, {%8,%9}, {%0,%1,%2,%3};"
        : "+f"(d0), "+f"(d1), "+f"(d2), "+f"(d3)
        : "r"(a0), "r"(a1), "r"(a2), "r"(a3), "r"(b0), "r"(b1));
}

// ---------------- init --------------------------------------------------------
__global__ void init_kernel() {
    int i = threadIdx.x;
    if (i < E) { g_counts[i] = 0; g_fill[i] = 0; }
}

// ---------------- fp32 -> fp16 conversion (x only) -----------------------------
__global__ __launch_bounds__(256) void conv_kernel(const float* __restrict__ in,
                                                   __half* __restrict__ out, int n8) {
    int i = blockIdx.x * blockDim.x + threadIdx.x;
    int stride = gridDim.x * blockDim.x;
    const float4* in4 = (const float4*)in;
    uint4* out8 = (uint4*)out;
    for (; i < n8; i += stride) {
        float4 a = in4[2 * i], b = in4[2 * i + 1];
        uint4 o;
        o.x = h2u(__floats2half2_rn(a.x, a.y));
        o.y = h2u(__floats2half2_rn(a.z, a.w));
        o.z = h2u(__floats2half2_rn(b.x, b.y));
        o.w = h2u(__floats2half2_rn(b.z, b.w));
        out8[i] = o;
    }
}

// ---------------- gating: 4 tokens per block ----------------------------------
__global__ __launch_bounds__(256) void gate_kernel(const float* __restrict__ x,
                                                   const float* __restrict__ gw) {
    __shared__ float xs[4][H];
    __shared__ float logits[4][E];
    const int t0 = blockIdx.x * 4;
    for (int i = threadIdx.x; i < 4 * H; i += 256)
        xs[i >> 11][i & (H - 1)] = x[(size_t)t0 * H + i];
    __syncthreads();

    const int warp = threadIdx.x >> 5, lane = threadIdx.x & 31;
    for (int ee = 0; ee < 8; ee++) {
        const int e = warp * 8 + ee;
        const float* wrow = gw + (size_t)e * H;
        float a0 = 0.f, a1 = 0.f, a2 = 0.f, a3 = 0.f;
        for (int h = lane; h < H; h += 32) {
            float wv = wrow[h];
            a0 = fmaf(wv, xs[0][h], a0);
            a1 = fmaf(wv, xs[1][h], a1);
            a2 = fmaf(wv, xs[2][h], a2);
            a3 = fmaf(wv, xs[3][h], a3);
        }
        #pragma unroll
        for (int o = 16; o; o >>= 1) {
            a0 += __shfl_xor_sync(0xffffffffu, a0, o);
            a1 += __shfl_xor_sync(0xffffffffu, a1, o);
            a2 += __shfl_xor_sync(0xffffffffu, a2, o);
            a3 += __shfl_xor_sync(0xffffffffu, a3, o);
        }
        if (lane == 0) {
            logits[0][e] = a0; logits[1][e] = a1;
            logits[2][e] = a2; logits[3][e] = a3;
        }
    }
    __syncthreads();

    if (warp < 4) {
        const int t = t0 + warp;
        float l0 = logits[warp][lane], l1 = logits[warp][lane + 32];
        int sel_i[TOPK]; float sel_v[TOPK];
        #pragma unroll
        for (int k = 0; k < TOPK; k++) {
            float v; int idx;
            if (l0 >= l1) { v = l0; idx = lane; } else { v = l1; idx = lane + 32; }
            #pragma unroll
            for (int o = 16; o; o >>= 1) {
                float ov = __shfl_xor_sync(0xffffffffu, v, o);
                int   oi = __shfl_xor_sync(0xffffffffu, idx, o);
                if (ov > v || (ov == v && oi < idx)) { v = ov; idx = oi; }
            }
            sel_i[k] = idx; sel_v[k] = v;
            if (idx == lane) l0 = -CUDART_INF_F;
            else if (idx == lane + 32) l1 = -CUDART_INF_F;
        }
        if (lane == 0) {
            float m = sel_v[0];
            float ww[TOPK], s = 0.f;
            #pragma unroll
            for (int k = 0; k < TOPK; k++) { ww[k] = __expf(sel_v[k] - m); s += ww[k]; }
            float inv = 1.f / s;
            #pragma unroll
            for (int k = 0; k < TOPK; k++) {
                g_topk_idx[t * TOPK + k] = sel_i[k];
                g_topk_w[t * TOPK + k] = ww[k] * inv;
                atomicAdd(&g_counts[sel_i[k]], 1);
            }
        }
    }
}

__global__ void scan_kernel() {
    if (threadIdx.x == 0) {
        int acc = 0;
        for (int e = 0; e < E; e++) {
            g_offsets[e] = acc;
            int c = g_counts[e];
            int n64 = c >> 6, rem = c & 63;
            int o32 = -1;
            if (rem > 32) n64 += 1;
            else if (rem > 0) o32 = acc + (n64 << 6);
            g_n64[e] = n64;
            g_off32[e] = o32;
            acc += c;
        }
        g_offsets[E] = acc;
    }
}

__global__ void scatter_kernel() {
    int i = blockIdx.x * blockDim.x + threadIdx.x;
    if (i >= NSLOT) return;
    int t = i / TOPK;
    int e = g_topk_idx[i];
    int pos = g_offsets[e] + atomicAdd(&g_fill[e], 1);
    g_slot_token[pos] = t;
    g_slot_of[i] = pos;
}

// =====================  Fused up-proj (w1 & w3 + SwiGLU)  ======================
// CTA: MT(64/32) x 128(N per mat) x 2 mats. 8 warps = 2 mat x 4 n; warp MT x 32.
// A fp16 (gathered) cp.async 3-stage; B fp32 reg-staged -> fp16 STS, 2-stage.
// One __syncthreads per k-chunk (32).
constexpr int UP_BROWB = 272;             // 128 halves data + 16B pad
constexpr int UP_BMATB = 32 * UP_BROWB;   // 8704
constexpr int UP_BSTGB = 2 * UP_BMATB;    // 17408
constexpr int UP_SMEM = 3 * (64 * 80) + 2 * UP_BSTGB;  // 50176

template <int MT>
__device__ __forceinline__ void up_tile(char* smem,
                                        const __half* __restrict__ X,
                                        const float* __restrict__ W1,
                                        const float* __restrict__ W3,
                                        __half* __restrict__ OUT,
                                        int e, int m0, int rend, int n0) {
    constexpr int ASTGB = MT * 80;
    constexpr int NCH = H / 32;  // 64
    const uint32_t bA = smem_u32(smem);
    const uint32_t bB = bA + 3 * ASTGB;

    const int tid = threadIdx.x, wid = tid >> 5, lane = tid & 31;
    const int gq = lane >> 2, tg = lane & 3;
    const int r8 = lane & 7, sel = lane >> 3;
    const int mat = wid >> 2, wn = wid & 3;
    const int nw = wn * 32;

    // A staging: MT rows x 4 x 16B
    const bool aact = tid < MT * 4;
    const int at = tid & (MT * 4 - 1);
    const int ar = at >> 2, aseg = at & 3;
    const int arow = m0 + ar;
    const bool aok = aact && arow < rend;
    const int asrc = aok ? g_slot_token[arow] : 0;
    const __half* aG = X + (size_t)asrc * H + aseg * 8;
    const int asz = aok ? 16 : 0;
    const uint32_t aS0 = bA + (uint32_t)(ar * 80 + aseg * 16);

    // B staging: 128 threads per mat; thread covers float offsets
    // bseg*4 + h*64 + j*16 (+0..3) of the 128-col row  (bytes: bseg*8 + h*128 + j*32)
    const int bmat = tid >> 7;
    const int bt = tid & 127;
    const int bk = bt >> 2, bseg = bt & 3;
    const float* bGsrc = (bmat ? W3 : W1) + (size_t)e * H * I + (size_t)bk * I + n0 + bseg * 4;
    const uint32_t bS0 = bB + (uint32_t)(bmat * UP_BMATB + bk * UP_BROWB + bseg * 8);

    uint32_t aRow[MT / 16];
    #pragma unroll
    for (int mf = 0; mf < MT / 16; mf++)
        aRow[mf] = (uint32_t)((mf * 16 + ((sel & 1) << 3) + r8) * 80);
    const uint32_t aColOff = (uint32_t)(((sel >> 1) << 3) * 2);
    uint32_t bCol[2];
    #pragma unroll
    for (int nb = 0; nb < 2; nb++)
        bCol[nb] = (uint32_t)((nw + nb * 16 + ((sel >> 1) << 3)) * 2);
    const uint32_t bRowOff = (uint32_t)((((sel & 1) << 3) + r8) * UP_BROWB);
    const uint32_t bMatOff = (uint32_t)(mat * UP_BMATB);

    float4 b4[4];
    auto ldgH = [&](int ci, int h) {
        const float* p = bGsrc + (size_t)ci * 32 * I + h * 64;
        #pragma unroll
        for (int j = 0; j < 4; j++) b4[j] = *(const float4*)(p + j * 16);
    };
    auto stsH = [&](int stage, int h) {
        const uint32_t d = bS0 + (uint32_t)(stage * UP_BSTGB + h * 128);
        #pragma unroll
        for (int j = 0; j < 4; j++) {
            uint32_t u0 = h2u(__floats2half2_rn(b4[j].x, b4[j].y));
            uint32_t u1 = h2u(__floats2half2_rn(b4[j].z, b4[j].w));
            asm volatile("st.shared.v2.b32 [%0], {%1,%2};"
                         :: "r"(d + j * 32), "r"(u0), "r"(u1) : "memory");
        }
    };
    auto cpaA = [&](int ci) {
        if (aact) cpa16(aS0 + (uint32_t)((ci % 3) * ASTGB), aG + ci * 32, asz);
        CP_COMMIT();
    };

    float acc[MT / 16][4][4];
    #pragma unroll
    for (int mf = 0; mf < MT / 16; mf++)
        #pragma unroll
        for (int j = 0; j < 4; j++)
            #pragma unroll
            for (int q = 0; q < 4; q++) acc[mf][j][q] = 0.f;

    ldgH(0, 0); stsH(0, 0);
    ldgH(0, 1); stsH(0, 1);
    cpaA(0); cpaA(1);

    for (int ci = 0; ci < NCH; ci++) {
        CP_WAIT(1);
        __syncthreads();
        if (ci + 2 < NCH) cpaA(ci + 2); else CP_COMMIT();

        const uint32_t aStg = bA + (uint32_t)((ci % 3) * ASTGB);
        const uint32_t bStg = bB + (uint32_t)((ci & 1) * UP_BSTGB) + bMatOff;
        const int nst = (ci + 1) & 1;
        const bool pf = (ci + 1 < NCH);
        if (pf) ldgH(ci + 1, 0);

        #pragma unroll
        for (int k16 = 0; k16 < 2; k16++) {
            const uint32_t kb = k16 * 16;
            uint32_t aF[MT / 16][4], bF[2][4];
            #pragma unroll
            for (int mf = 0; mf < MT / 16; mf++)
                LDM_X4(aF[mf][0], aF[mf][1], aF[mf][2], aF[mf][3],
                       aStg + aRow[mf] + kb * 2 + aColOff);
            #pragma unroll
            for (int nb = 0; nb < 2; nb++)
                LDM_X4T(bF[nb][0], bF[nb][1], bF[nb][2], bF[nb][3],
                        bStg + kb * UP_BROWB + bRowOff + bCol[nb]);
            #pragma unroll
            for (int mf = 0; mf < MT / 16; mf++)
                #pragma unroll
                for (int j = 0; j < 4; j++)
                    mma16816(acc[mf][j][0], acc[mf][j][1], acc[mf][j][2], acc[mf][j][3],
                             aF[mf][0], aF[mf][1], aF[mf][2], aF[mf][3],
                             bF[j >> 1][(j & 1) * 2], bF[j >> 1][(j & 1) * 2 + 1]);
            if (k16 == 0 && pf) { stsH(nst, 0); ldgH(ci + 1, 1); }
        }
        if (pf) stsH(nst, 1);
    }
    __syncthreads();

    // epilogue: exchange g via smem, act = silu(g) * u
    float* exch = (float*)smem;  // MT x 132 floats
    if (mat == 0) {
        #pragma unroll
        for (int mf = 0; mf < MT / 16; mf++)
            #pragma unroll
            for (int hr = 0; hr < 2; hr++) {
                const int lr = mf * 16 + gq + hr * 8;
                #pragma unroll
                for (int j = 0; j < 4; j++) {
                    const int lc = nw + j * 8 + tg * 2;
                    exch[lr * 132 + lc] = acc[mf][j][hr * 2 + 0];
                    exch[lr * 132 + lc + 1] = acc[mf][j][hr * 2 + 1];
                }
            }
    }
    __syncthreads();
    if (mat == 1) {
        #pragma unroll
        for (int mf = 0; mf < MT / 16; mf++)
            #pragma unroll
            for (int hr = 0; hr < 2; hr++) {
                const int lr = mf * 16 + gq + hr * 8;
                const int row = m0 + lr;
                if (row >= rend) continue;
                #pragma unroll
                for (int j = 0; j < 4; j++) {
                    const int lc = nw + j * 8 + tg * 2;
                    float g0 = exch[lr * 132 + lc];
                    float g1 = exch[lr * 132 + lc + 1];
                    float u0 = acc[mf][j][hr * 2 + 0];
                    float u1 = acc[mf][j][hr * 2 + 1];
                    float v0 = u0 * g0 / (1.f + __expf(-g0));
                    float v1 = u1 * g1 / (1.f + __expf(-g1));
                    __half2* dst = (__half2*)(OUT + (size_t)row * I + n0 + lc);
                    *dst = __floats2half2_rn(v0, v1);
                }
            }
    }
}

__global__ __launch_bounds__(256, 2) void up_gemm(const __half* __restrict__ X,
                                                  const float* __restrict__ W1,
                                                  const float* __restrict__ W3,
                                                  __half* __restrict__ OUT) {
    extern __shared__ char smem[];
    const int e = blockIdx.y;
    const int n64 = g_n64[e];
    const int bx = blockIdx.x;
    const int rend = g_offsets[e + 1];
    const int n0 = blockIdx.z * 128;
    if (bx < n64) {
        up_tile<64>(smem, X, W1, W3, OUT, e, g_offsets[e] + bx * 64, rend, n0);
    } else if (bx == n64) {
        const int m0 = g_off32[e];
        if (m0 >= 0) up_tile<32>(smem, X, W1, W3, OUT, e, m0, rend, n0);
    }
}

// =====================  Down-proj (w2)  ========================================
// CTA: MT x 256. 8 warps = 8 n; warp MT x 32.
constexpr int DN_BROWB = 528;             // 256 halves data + 16B pad
constexpr int DN_BSTGB = 32 * DN_BROWB;   // 16896
constexpr int DN_SMEM = 3 * (64 * 80) + 2 * DN_BSTGB;  // 49152

template <int MT>
__device__ __forceinline__ void down_tile(char* smem,
                                          const __half* __restrict__ A,
                                          const float* __restrict__ W2,
                                          __half* __restrict__ OUT,
                                          int e, int m0, int rend, int n0) {
    constexpr int ASTGB = MT * 80;
    constexpr int NCH = I / 32;  // 24
    const uint32_t bA = smem_u32(smem);
    const uint32_t bB = bA + 3 * ASTGB;

    const int tid = threadIdx.x, wid = tid >> 5, lane = tid & 31;
    const int gq = lane >> 2, tg = lane & 3;
    const int r8 = lane & 7, sel = lane >> 3;
    const int nw = wid * 32;

    const bool aact = tid < MT * 4;
    const int at = tid & (MT * 4 - 1);
    const int ar = at >> 2, aseg = at & 3;
    const int arow = m0 + ar;
    const bool aok = aact && arow < rend;
    const __half* aG = A + (size_t)(aok ? arow : 0) * I + aseg * 8;
    const int asz = aok ? 16 : 0;
    const uint32_t aS0 = bA + (uint32_t)(ar * 80 + aseg * 16);

    // B: 256 threads; thread covers float offsets bseg*4 + h*128 + j*32 (+0..3)
    // of the 256-col row  (bytes: bseg*8 + h*256 + j*64)
    const int bk = tid >> 3, bseg = tid & 7;
    const float* bGsrc = W2 + (size_t)e * I * H + (size_t)bk * H + n0 + bseg * 4;
    const uint32_t bS0 = bB + (uint32_t)(bk * DN_BROWB + bseg * 8);

    uint32_t aRow[MT / 16];
    #pragma unroll
    for (int mf = 0; mf < MT / 16; mf++)
        aRow[mf] = (uint32_t)((mf * 16 + ((sel & 1) << 3) + r8) * 80);
    const uint32_t aColOff = (uint32_t)(((sel >> 1) << 3) * 2);
    uint32_t bCol[2];
    #pragma unroll
    for (int nb = 0; nb < 2; nb++)
        bCol[nb] = (uint32_t)((nw + nb * 16 + ((sel >> 1) << 3)) * 2);
    const uint32_t bRowOff = (uint32_t)((((sel & 1) << 3) + r8) * DN_BROWB);

    float4 b4[4];
    auto ldgH = [&](int ci, int h) {
        const float* p = bGsrc + (size_t)ci * 32 * H + h * 128;
        #pragma unroll
        for (int j = 0; j < 4; j++) b4[j] = *(const float4*)(p + j * 32);
    };
    auto stsH = [&](int stage, int h) {
        const uint32_t d = bS0 + (uint32_t)(stage * DN_BSTGB + h * 256);
        #pragma unroll
        for (int j = 0; j < 4; j++) {
            uint32_t u0 = h2u(__floats2half2_rn(b4[j].x, b4[j].y));
            uint32_t u1 = h2u(__floats2half2_rn(b4[j].z, b4[j].w));
            asm volatile("st.shared.v2.b32 [%0], {%1,%2};"
                         :: "r"(d + j * 64), "r"(u0), "r"(u1) : "memory");
        }
    };
    auto cpaA = [&](int ci) {
        if (aact) cpa16(aS0 + (uint32_t)((ci % 3) * ASTGB), aG + ci * 32, asz);
        CP_COMMIT();
    };

    float acc[MT / 16][4][4];
    #pragma unroll
    for (int mf = 0; mf < MT / 16; mf++)
        #pragma unroll
        for (int j = 0; j < 4; j++)
            #pragma unroll
            for (int q = 0; q < 4; q++) acc[mf][j][q] = 0.f;

    ldgH(0, 0); stsH(0, 0);
    ldgH(0, 1); stsH(0, 1);
    cpaA(0); cpaA(1);

    for (int ci = 0; ci < NCH; ci++) {
        CP_WAIT(1);
        __syncthreads();
        if (ci + 2 < NCH) cpaA(ci + 2); else CP_COMMIT();

        const uint32_t aStg = bA + (uint32_t)((ci % 3) * ASTGB);
        const uint32_t bStg = bB + (uint32_t)((ci & 1) * DN_BSTGB);
        const int nst = (ci + 1) & 1;
        const bool pf = (ci + 1 < NCH);
        if (pf) ldgH(ci + 1, 0);

        #pragma unroll
        for (int k16 = 0; k16 < 2; k16++) {
            const uint32_t kb = k16 * 16;
            uint32_t aF[MT / 16][4], bF[2][4];
            #pragma unroll
            for (int mf = 0; mf < MT / 16; mf++)
                LDM_X4(aF[mf][0], aF[mf][1], aF[mf][2], aF[mf][3],
                       aStg + aRow[mf] + kb * 2 + aColOff);
            #pragma unroll
            for (int nb = 0; nb < 2; nb++)
                LDM_X4T(bF[nb][0], bF[nb][1], bF[nb][2], bF[nb][3],
                        bStg + kb * DN_BROWB + bRowOff + bCol[nb]);
            #pragma unroll
            for (int mf = 0; mf < MT / 16; mf++)
                #pragma unroll
                for (int j = 0; j < 4; j++)
                    mma16816(acc[mf][j][0], acc[mf][j][1], acc[mf][j][2], acc[mf][j][3],
                             aF[mf][0], aF[mf][1], aF[mf][2], aF[mf][3],
                             bF[j >> 1][(j & 1) * 2], bF[j >> 1][(j & 1) * 2 + 1]);
            if (k16 == 0 && pf) { stsH(nst, 0); ldgH(ci + 1, 1); }
        }
        if (pf) stsH(nst, 1);
    }

    #pragma unroll
    for (int mf = 0; mf < MT / 16; mf++)
        #pragma unroll
        for (int hr = 0; hr < 2; hr++) {
            const int row = m0 + mf * 16 + gq + hr * 8;
            if (row >= rend) continue;
            #pragma unroll
            for (int j = 0; j < 4; j++) {
                const int col = n0 + nw + j * 8 + tg * 2;
                __half2* dst = (__half2*)(OUT + (size_t)row * H + col);
                *dst = __floats2half2_rn(acc[mf][j][hr * 2 + 0], acc[mf][j][hr * 2 + 1]);
            }
        }
}

__global__ __launch_bounds__(256, 2) void down_gemm(const __half* __restrict__ A,
                                                    const float* __restrict__ W2,
                                                    __half* __restrict__ OUT) {
    extern __shared__ char smem[];
    const int e = blockIdx.y;
    const int n64 = g_n64[e];
    const int bx = blockIdx.x;
    const int rend = g_offsets[e + 1];
    const int n0 = blockIdx.z * 256;
    if (bx < n64) {
        down_tile<64>(smem, A, W2, OUT, e, g_offsets[e] + bx * 64, rend, n0);
    } else if (bx == n64) {
        const int m0 = g_off32[e];
        if (m0 >= 0) down_tile<32>(smem, A, W2, OUT, e, m0, rend, n0);
    }
}

// ---------------- combine: out[t] = sum_k w[t,k] * ybuf[slot_of[t,k]] ----------
__global__ __launch_bounds__(256) void combine_kernel(float* __restrict__ out) {
    const int t = blockIdx.x;
    __shared__ float w[TOPK];
    __shared__ int rowi[TOPK];
    if (threadIdx.x < TOPK) {
        w[threadIdx.x] = g_topk_w[t * TOPK + threadIdx.x];
        rowi[threadIdx.x] = g_slot_of[t * TOPK + threadIdx.x];
    }
    __syncthreads();
    const int j = threadIdx.x;  // 256 threads x 8 outputs = 2048 = H
    float acc[8];
    #pragma unroll
    for (int q = 0; q < 8; q++) acc[q] = 0.f;
    #pragma unroll
    for (int k = 0; k < TOPK; k++) {
        const uint4 v = *(const uint4*)(g_ybuf + (size_t)rowi[k] * H + j * 8);
        const __half2* hp = (const __half2*)&v;
        const float wk = w[k];
        #pragma unroll
        for (int q = 0; q < 4; q++) {
            float2 f = __half22float2(hp[q]);
            acc[2 * q + 0] = fmaf(wk, f.x, acc[2 * q + 0]);
            acc[2 * q + 1] = fmaf(wk, f.y, acc[2 * q + 1]);
        }
    }
    float4* orow = (float4*)(out + (size_t)t * H + j * 8);
    orow[0] = make_float4(acc[0], acc[1], acc[2], acc[3]);
    orow[1] = make_float4(acc[4], acc[5], acc[6], acc[7]);
}

// ---------------- launch ------------------------------------------------------
extern "C" void kernel_launch(void* const* d_in, const int* in_sizes, int n_in,
                              void* d_out, int out_size) {
    const float* x  = (const float*)d_in[0];
    const float* gw = (const float*)d_in[1];
    const float* w1 = (const float*)d_in[2];
    const float* w3 = (const float*)d_in[3];
    const float* w2 = (const float*)d_in[4];
    float* out = (float*)d_out;

    __half *xh, *abuf, *ybuf;
    cudaGetSymbolAddress((void**)&xh, g_xh);
    cudaGetSymbolAddress((void**)&abuf, g_abuf);
    cudaGetSymbolAddress((void**)&ybuf, g_ybuf);

    cudaFuncSetAttribute(up_gemm, cudaFuncAttributeMaxDynamicSharedMemorySize, UP_SMEM);
    cudaFuncSetAttribute(down_gemm, cudaFuncAttributeMaxDynamicSharedMemorySize, DN_SMEM);

    init_kernel<<<1, 64>>>();
    gate_kernel<<<T / 4, 256>>>(x, gw);
    scan_kernel<<<1, 32>>>();
    scatter_kernel<<<(NSLOT + 255) / 256, 256>>>();
    conv_kernel<<<2048, 256>>>(x, xh, T * H / 8);

    // fused up-proj: act = silu(X@w1) * (X@w3)
    dim3 gridU(8, E, I / 128);
    up_gemm<<<gridU, 256, UP_SMEM>>>(xh, w1, w3, abuf);

    // down-proj: ybuf = act @ w2
    dim3 gridD(8, E, H / 256);
    down_gemm<<<gridD, 256, DN_SMEM>>>(abuf, w2, ybuf);

    combine_kernel<<<T, 256>>>(out);
}

// round 10
// speedup vs baseline: 6.6431x; 1.0759x over previous
#include <cuda_runtime.h>
#include <cuda_fp16.h>
#include <math.h>
#include <math_constants.h>
#include <cstdint>

// Problem constants (Qwen3 MoE: B=1, S=1024, H=2048, E=64, I=768, top_k=8)
constexpr int T = 1024;
constexpr int H = 2048;
constexpr int E = 64;
constexpr int I = 768;
constexpr int TOPK = 8;
constexpr int NSLOT = T * TOPK;  // 8192

// ---------------- scratch (device globals) ------------------------------------
__device__ int   g_topk_idx[NSLOT];
__device__ float g_topk_w[NSLOT];
__device__ int   g_counts[E];
__device__ int   g_offsets[E + 1];
__device__ int   g_n64[E];      // number of M64 tiles per expert
__device__ int   g_off32[E];    // slot offset of M32 tail tile, or -1
__device__ int   g_fill[E];
__device__ int   g_slot_token[NSLOT];
__device__ int   g_slot_of[NSLOT];
__device__ __align__(16) __half g_xh[(size_t)T * H];
__device__ __align__(16) __half g_abuf[(size_t)NSLOT * I];   // act (fp16)
__device__ __align__(16) __half g_ybuf[(size_t)NSLOT * H];   // y per slot (fp16)

// ---------------- PTX helpers -------------------------------------------------
__device__ __forceinline__ uint32_t smem_u32(const void* p) {
    uint32_t a;
    asm("{ .reg .u64 t; cvta.to.shared.u64 t, %1; cvt.u32.u64 %0, t; }" : "=r"(a) : "l"(p));
    return a;
}
__device__ __forceinline__ uint32_t h2u(__half2 h) {
    union { __half2 h; uint32_t u; } c; c.h = h; return c.u;
}
__device__ __forceinline__ void cpa16(uint32_t dst, const void* src, int sz) {
    asm volatile("cp.async.cg.shared.global [%0], [%1], 16, %2;"
                 :: "r"(dst), "l"(src), "r"(sz) : "memory");
}
#define CP_COMMIT() asm volatile("cp.async.commit_group;" ::: "memory")
#define CP_WAIT(n)  asm volatile("cp.async.wait_group %0;" :: "n"(n) : "memory")

#define LDM_X4(r0, r1, r2, r3, a) \
    asm volatile("ldmatrix.sync.aligned.m8n8.x4.shared.b16 {%0,%1,%2,%3}, [%4];" \
                 : "=r"(r0), "=r"(r1), "=r"(r2), "=r"(r3) : "r"(a))
#define LDM_X4T(r0, r1, r2, r3, a) \
    asm volatile("ldmatrix.sync.aligned.m8n8.x4.trans.shared.b16 {%0,%1,%2,%3}, [%4];" \
                 : "=r"(r0), "=r"(r1), "=r"(r2), "=r"(r3) : "r"(a))

__device__ __forceinline__ void mma16816(float& d0, float& d1, float& d2, float& d3,
                                         uint32_t a0, uint32_t a1, uint32_t a2, uint32_t a3,
                                         uint32_t b0, uint32_t b1) {
    asm volatile(
        "mma.sync.aligned.m16n8k16.row.col.f32.f16.f16.f32 "
        "{%0,%1,%2,%3}, {%4,%5,%6,%7}, {%8,%9}, {%0,%1,%2,%3};"
        : "+f"(d0), "+f"(d1), "+f"(d2), "+f"(d3)
        : "r"(a0), "r"(a1), "r"(a2), "r"(a3), "r"(b0), "r"(b1));
}

// ---------------- init --------------------------------------------------------
__global__ void init_kernel() {
    int i = threadIdx.x;
    if (i < E) { g_counts[i] = 0; g_fill[i] = 0; }
}

// ---------------- gating: 4 tokens per block; also emits fp16 x ----------------
__global__ __launch_bounds__(256) void gate_kernel(const float* __restrict__ x,
                                                   const float* __restrict__ gw,
                                                   __half* __restrict__ xh) {
    __shared__ float xs[4][H];
    __shared__ float logits[4][E];
    const int t0 = blockIdx.x * 4;
    for (int i = threadIdx.x; i < 4 * H; i += 256)
        xs[i >> 11][i & (H - 1)] = x[(size_t)t0 * H + i];
    __syncthreads();

    // emit fp16 copy of x (from smem; no extra gmem read)
    {
        const float* xf = &xs[0][0];
        for (int i = threadIdx.x; i < 2 * H; i += 256) {
            __half2 h = __floats2half2_rn(xf[2 * i], xf[2 * i + 1]);
            *(__half2*)(xh + (size_t)t0 * H + 2 * i) = h;
        }
    }

    const int warp = threadIdx.x >> 5, lane = threadIdx.x & 31;
    for (int ee = 0; ee < 8; ee++) {
        const int e = warp * 8 + ee;
        const float* wrow = gw + (size_t)e * H;
        float a0 = 0.f, a1 = 0.f, a2 = 0.f, a3 = 0.f;
        for (int h = lane; h < H; h += 32) {
            float wv = wrow[h];
            a0 = fmaf(wv, xs[0][h], a0);
            a1 = fmaf(wv, xs[1][h], a1);
            a2 = fmaf(wv, xs[2][h], a2);
            a3 = fmaf(wv, xs[3][h], a3);
        }
        #pragma unroll
        for (int o = 16; o; o >>= 1) {
            a0 += __shfl_xor_sync(0xffffffffu, a0, o);
            a1 += __shfl_xor_sync(0xffffffffu, a1, o);
            a2 += __shfl_xor_sync(0xffffffffu, a2, o);
            a3 += __shfl_xor_sync(0xffffffffu, a3, o);
        }
        if (lane == 0) {
            logits[0][e] = a0; logits[1][e] = a1;
            logits[2][e] = a2; logits[3][e] = a3;
        }
    }
    __syncthreads();

    if (warp < 4) {
        const int t = t0 + warp;
        float l0 = logits[warp][lane], l1 = logits[warp][lane + 32];
        int sel_i[TOPK]; float sel_v[TOPK];
        #pragma unroll
        for (int k = 0; k < TOPK; k++) {
            float v; int idx;
            if (l0 >= l1) { v = l0; idx = lane; } else { v = l1; idx = lane + 32; }
            #pragma unroll
            for (int o = 16; o; o >>= 1) {
                float ov = __shfl_xor_sync(0xffffffffu, v, o);
                int   oi = __shfl_xor_sync(0xffffffffu, idx, o);
                if (ov > v || (ov == v && oi < idx)) { v = ov; idx = oi; }
            }
            sel_i[k] = idx; sel_v[k] = v;
            if (idx == lane) l0 = -CUDART_INF_F;
            else if (idx == lane + 32) l1 = -CUDART_INF_F;
        }
        if (lane == 0) {
            float m = sel_v[0];
            float ww[TOPK], s = 0.f;
            #pragma unroll
            for (int k = 0; k < TOPK; k++) { ww[k] = __expf(sel_v[k] - m); s += ww[k]; }
            float inv = 1.f / s;
            #pragma unroll
            for (int k = 0; k < TOPK; k++) {
                g_topk_idx[t * TOPK + k] = sel_i[k];
                g_topk_w[t * TOPK + k] = ww[k] * inv;
                atomicAdd(&g_counts[sel_i[k]], 1);
            }
        }
    }
}

__global__ void scan_kernel() {
    if (threadIdx.x == 0) {
        int acc = 0;
        for (int e = 0; e < E; e++) {
            g_offsets[e] = acc;
            int c = g_counts[e];
            int n64 = c >> 6, rem = c & 63;
            int o32 = -1;
            if (rem > 32) n64 += 1;
            else if (rem > 0) o32 = acc + (n64 << 6);
            g_n64[e] = n64;
            g_off32[e] = o32;
            acc += c;
        }
        g_offsets[E] = acc;
    }
}

__global__ void scatter_kernel() {
    int i = blockIdx.x * blockDim.x + threadIdx.x;
    if (i >= NSLOT) return;
    int t = i / TOPK;
    int e = g_topk_idx[i];
    int pos = g_offsets[e] + atomicAdd(&g_fill[e], 1);
    g_slot_token[pos] = t;
    g_slot_of[i] = pos;
}

// =====================  Fused up-proj (w1 & w3 + SwiGLU)  ======================
// CTA: MT(64/32) x 128(N per mat) x 2 mats. 8 warps = 2 mat x 4 n; warp MT x 32.
// A fp16 (gathered) cp.async 3-stage. B fp32 reg-prefetched a FULL chunk ahead
// (both halves LDG'd at chunk start; STS'd as halves free up), 2-stage fp16.
constexpr int UP_BROWB = 272;             // 128 halves data + 16B pad
constexpr int UP_BMATB = 32 * UP_BROWB;   // 8704
constexpr int UP_BSTGB = 2 * UP_BMATB;    // 17408
constexpr int UP_SMEM = 3 * (64 * 80) + 2 * UP_BSTGB;  // 50176

template <int MT>
__device__ __forceinline__ void up_tile(char* smem,
                                        const __half* __restrict__ X,
                                        const float* __restrict__ W1,
                                        const float* __restrict__ W3,
                                        __half* __restrict__ OUT,
                                        int e, int m0, int rend, int n0) {
    constexpr int ASTGB = MT * 80;
    constexpr int NCH = H / 32;  // 64
    const uint32_t bA = smem_u32(smem);
    const uint32_t bB = bA + 3 * ASTGB;

    const int tid = threadIdx.x, wid = tid >> 5, lane = tid & 31;
    const int gq = lane >> 2, tg = lane & 3;
    const int r8 = lane & 7, sel = lane >> 3;
    const int mat = wid >> 2, wn = wid & 3;
    const int nw = wn * 32;

    // A staging: MT rows x 4 x 16B
    const bool aact = tid < MT * 4;
    const int at = tid & (MT * 4 - 1);
    const int ar = at >> 2, aseg = at & 3;
    const int arow = m0 + ar;
    const bool aok = aact && arow < rend;
    const int asrc = aok ? g_slot_token[arow] : 0;
    const __half* aG = X + (size_t)asrc * H + aseg * 8;
    const int asz = aok ? 16 : 0;
    const uint32_t aS0 = bA + (uint32_t)(ar * 80 + aseg * 16);

    // B staging: 128 threads per mat; thread covers float offsets
    // bseg*4 + h*64 + j*16 (+0..3)  (bytes: bseg*8 + h*128 + j*32)
    const int bmat = tid >> 7;
    const int bt = tid & 127;
    const int bk = bt >> 2, bseg = bt & 3;
    const float* bGsrc = (bmat ? W3 : W1) + (size_t)e * H * I + (size_t)bk * I + n0 + bseg * 4;
    const uint32_t bS0 = bB + (uint32_t)(bmat * UP_BMATB + bk * UP_BROWB + bseg * 8);

    uint32_t aRow[MT / 16];
    #pragma unroll
    for (int mf = 0; mf < MT / 16; mf++)
        aRow[mf] = (uint32_t)((mf * 16 + ((sel & 1) << 3) + r8) * 80);
    const uint32_t aColOff = (uint32_t)(((sel >> 1) << 3) * 2);
    uint32_t bCol[2];
    #pragma unroll
    for (int nb = 0; nb < 2; nb++)
        bCol[nb] = (uint32_t)((nw + nb * 16 + ((sel >> 1) << 3)) * 2);
    const uint32_t bRowOff = (uint32_t)((((sel & 1) << 3) + r8) * UP_BROWB);
    const uint32_t bMatOff = (uint32_t)(mat * UP_BMATB);

    float4 b4[8];
    auto ldgB2 = [&](int ci) {   // both halves of next chunk
        const float* p = bGsrc + (size_t)ci * 32 * I;
        #pragma unroll
        for (int j = 0; j < 4; j++) b4[j] = *(const float4*)(p + j * 16);
        #pragma unroll
        for (int j = 0; j < 4; j++) b4[4 + j] = *(const float4*)(p + 64 + j * 16);
    };
    auto stsH = [&](int stage, int h) {
        const uint32_t d = bS0 + (uint32_t)(stage * UP_BSTGB + h * 128);
        #pragma unroll
        for (int j = 0; j < 4; j++) {
            uint32_t u0 = h2u(__floats2half2_rn(b4[4 * h + j].x, b4[4 * h + j].y));
            uint32_t u1 = h2u(__floats2half2_rn(b4[4 * h + j].z, b4[4 * h + j].w));
            asm volatile("st.shared.v2.b32 [%0], {%1,%2};"
                         :: "r"(d + j * 32), "r"(u0), "r"(u1) : "memory");
        }
    };
    auto cpaA = [&](int ci) {
        if (aact) cpa16(aS0 + (uint32_t)((ci % 3) * ASTGB), aG + ci * 32, asz);
        CP_COMMIT();
    };

    float acc[MT / 16][4][4];
    #pragma unroll
    for (int mf = 0; mf < MT / 16; mf++)
        #pragma unroll
        for (int j = 0; j < 4; j++)
            #pragma unroll
            for (int q = 0; q < 4; q++) acc[mf][j][q] = 0.f;

    ldgB2(0); stsH(0, 0); stsH(0, 1);
    cpaA(0); cpaA(1);

    for (int ci = 0; ci < NCH; ci++) {
        CP_WAIT(1);
        __syncthreads();
        if (ci + 2 < NCH) cpaA(ci + 2); else CP_COMMIT();

        const uint32_t aStg = bA + (uint32_t)((ci % 3) * ASTGB);
        const uint32_t bStg = bB + (uint32_t)((ci & 1) * UP_BSTGB) + bMatOff;
        const int nst = (ci + 1) & 1;
        const bool pf = (ci + 1 < NCH);
        if (pf) ldgB2(ci + 1);     // full-chunk LDG->STS slack

        #pragma unroll
        for (int k16 = 0; k16 < 2; k16++) {
            const uint32_t kb = k16 * 16;
            uint32_t aF[MT / 16][4], bF[2][4];
            #pragma unroll
            for (int mf = 0; mf < MT / 16; mf++)
                LDM_X4(aF[mf][0], aF[mf][1], aF[mf][2], aF[mf][3],
                       aStg + aRow[mf] + kb * 2 + aColOff);
            #pragma unroll
            for (int nb = 0; nb < 2; nb++)
                LDM_X4T(bF[nb][0], bF[nb][1], bF[nb][2], bF[nb][3],
                        bStg + kb * UP_BROWB + bRowOff + bCol[nb]);
            #pragma unroll
            for (int mf = 0; mf < MT / 16; mf++)
                #pragma unroll
                for (int j = 0; j < 4; j++)
                    mma16816(acc[mf][j][0], acc[mf][j][1], acc[mf][j][2], acc[mf][j][3],
                             aF[mf][0], aF[mf][1], aF[mf][2], aF[mf][3],
                             bF[j >> 1][(j & 1) * 2], bF[j >> 1][(j & 1) * 2 + 1]);
            if (k16 == 0 && pf) stsH(nst, 0);
        }
        if (pf) stsH(nst, 1);
    }
    __syncthreads();

    // epilogue: exchange g via smem, act = silu(g) * u
    float* exch = (float*)smem;  // MT x 132 floats
    if (mat == 0) {
        #pragma unroll
        for (int mf = 0; mf < MT / 16; mf++)
            #pragma unroll
            for (int hr = 0; hr < 2; hr++) {
                const int lr = mf * 16 + gq + hr * 8;
                #pragma unroll
                for (int j = 0; j < 4; j++) {
                    const int lc = nw + j * 8 + tg * 2;
                    exch[lr * 132 + lc] = acc[mf][j][hr * 2 + 0];
                    exch[lr * 132 + lc + 1] = acc[mf][j][hr * 2 + 1];
                }
            }
    }
    __syncthreads();
    if (mat == 1) {
        #pragma unroll
        for (int mf = 0; mf < MT / 16; mf++)
            #pragma unroll
            for (int hr = 0; hr < 2; hr++) {
                const int lr = mf * 16 + gq + hr * 8;
                const int row = m0 + lr;
                if (row >= rend) continue;
                #pragma unroll
                for (int j = 0; j < 4; j++) {
                    const int lc = nw + j * 8 + tg * 2;
                    float g0 = exch[lr * 132 + lc];
                    float g1 = exch[lr * 132 + lc + 1];
                    float u0 = acc[mf][j][hr * 2 + 0];
                    float u1 = acc[mf][j][hr * 2 + 1];
                    float v0 = u0 * g0 / (1.f + __expf(-g0));
                    float v1 = u1 * g1 / (1.f + __expf(-g1));
                    __half2* dst = (__half2*)(OUT + (size_t)row * I + n0 + lc);
                    *dst = __floats2half2_rn(v0, v1);
                }
            }
    }
}

__global__ __launch_bounds__(256, 2) void up_gemm(const __half* __restrict__ X,
                                                  const float* __restrict__ W1,
                                                  const float* __restrict__ W3,
                                                  __half* __restrict__ OUT) {
    extern __shared__ char smem[];
    const int e = blockIdx.y;
    const int n64 = g_n64[e];
    const int bx = blockIdx.x;
    const int rend = g_offsets[e + 1];
    const int n0 = blockIdx.z * 128;
    if (bx < n64) {
        up_tile<64>(smem, X, W1, W3, OUT, e, g_offsets[e] + bx * 64, rend, n0);
    } else if (bx == n64) {
        const int m0 = g_off32[e];
        if (m0 >= 0) up_tile<32>(smem, X, W1, W3, OUT, e, m0, rend, n0);
    }
}

// =====================  Down-proj (w2)  ========================================
// CTA: MT x 256. 8 warps = 8 n; warp MT x 32.
constexpr int DN_BROWB = 528;             // 256 halves data + 16B pad
constexpr int DN_BSTGB = 32 * DN_BROWB;   // 16896
constexpr int DN_SMEM = 3 * (64 * 80) + 2 * DN_BSTGB;  // 49152

template <int MT>
__device__ __forceinline__ void down_tile(char* smem,
                                          const __half* __restrict__ A,
                                          const float* __restrict__ W2,
                                          __half* __restrict__ OUT,
                                          int e, int m0, int rend, int n0) {
    constexpr int ASTGB = MT * 80;
    constexpr int NCH = I / 32;  // 24
    const uint32_t bA = smem_u32(smem);
    const uint32_t bB = bA + 3 * ASTGB;

    const int tid = threadIdx.x, wid = tid >> 5, lane = tid & 31;
    const int gq = lane >> 2, tg = lane & 3;
    const int r8 = lane & 7, sel = lane >> 3;
    const int nw = wid * 32;

    const bool aact = tid < MT * 4;
    const int at = tid & (MT * 4 - 1);
    const int ar = at >> 2, aseg = at & 3;
    const int arow = m0 + ar;
    const bool aok = aact && arow < rend;
    const __half* aG = A + (size_t)(aok ? arow : 0) * I + aseg * 8;
    const int asz = aok ? 16 : 0;
    const uint32_t aS0 = bA + (uint32_t)(ar * 80 + aseg * 16);

    // B: 256 threads; thread covers float offsets bseg*4 + h*128 + j*32 (+0..3)
    // (bytes: bseg*8 + h*256 + j*64)
    const int bk = tid >> 3, bseg = tid & 7;
    const float* bGsrc = W2 + (size_t)e * I * H + (size_t)bk * H + n0 + bseg * 4;
    const uint32_t bS0 = bB + (uint32_t)(bk * DN_BROWB + bseg * 8);

    uint32_t aRow[MT / 16];
    #pragma unroll
    for (int mf = 0; mf < MT / 16; mf++)
        aRow[mf] = (uint32_t)((mf * 16 + ((sel & 1) << 3) + r8) * 80);
    const uint32_t aColOff = (uint32_t)(((sel >> 1) << 3) * 2);
    uint32_t bCol[2];
    #pragma unroll
    for (int nb = 0; nb < 2; nb++)
        bCol[nb] = (uint32_t)((nw + nb * 16 + ((sel >> 1) << 3)) * 2);
    const uint32_t bRowOff = (uint32_t)((((sel & 1) << 3) + r8) * DN_BROWB);

    float4 b4[8];
    auto ldgB2 = [&](int ci) {
        const float* p = bGsrc + (size_t)ci * 32 * H;
        #pragma unroll
        for (int j = 0; j < 4; j++) b4[j] = *(const float4*)(p + j * 32);
        #pragma unroll
        for (int j = 0; j < 4; j++) b4[4 + j] = *(const float4*)(p + 128 + j * 32);
    };
    auto stsH = [&](int stage, int h) {
        const uint32_t d = bS0 + (uint32_t)(stage * DN_BSTGB + h * 256);
        #pragma unroll
        for (int j = 0; j < 4; j++) {
            uint32_t u0 = h2u(__floats2half2_rn(b4[4 * h + j].x, b4[4 * h + j].y));
            uint32_t u1 = h2u(__floats2half2_rn(b4[4 * h + j].z, b4[4 * h + j].w));
            asm volatile("st.shared.v2.b32 [%0], {%1,%2};"
                         :: "r"(d + j * 64), "r"(u0), "r"(u1) : "memory");
        }
    };
    auto cpaA = [&](int ci) {
        if (aact) cpa16(aS0 + (uint32_t)((ci % 3) * ASTGB), aG + ci * 32, asz);
        CP_COMMIT();
    };

    float acc[MT / 16][4][4];
    #pragma unroll
    for (int mf = 0; mf < MT / 16; mf++)
        #pragma unroll
        for (int j = 0; j < 4; j++)
            #pragma unroll
            for (int q = 0; q < 4; q++) acc[mf][j][q] = 0.f;

    ldgB2(0); stsH(0, 0); stsH(0, 1);
    cpaA(0); cpaA(1);

    for (int ci = 0; ci < NCH; ci++) {
        CP_WAIT(1);
        __syncthreads();
        if (ci + 2 < NCH) cpaA(ci + 2); else CP_COMMIT();

        const uint32_t aStg = bA + (uint32_t)((ci % 3) * ASTGB);
        const uint32_t bStg = bB + (uint32_t)((ci & 1) * DN_BSTGB);
        const int nst = (ci + 1) & 1;
        const bool pf = (ci + 1 < NCH);
        if (pf) ldgB2(ci + 1);

        #pragma unroll
        for (int k16 = 0; k16 < 2; k16++) {
            const uint32_t kb = k16 * 16;
            uint32_t aF[MT / 16][4], bF[2][4];
            #pragma unroll
            for (int mf = 0; mf < MT / 16; mf++)
                LDM_X4(aF[mf][0], aF[mf][1], aF[mf][2], aF[mf][3],
                       aStg + aRow[mf] + kb * 2 + aColOff);
            #pragma unroll
            for (int nb = 0; nb < 2; nb++)
                LDM_X4T(bF[nb][0], bF[nb][1], bF[nb][2], bF[nb][3],
                        bStg + kb * DN_BROWB + bRowOff + bCol[nb]);
            #pragma unroll
            for (int mf = 0; mf < MT / 16; mf++)
                #pragma unroll
                for (int j = 0; j < 4; j++)
                    mma16816(acc[mf][j][0], acc[mf][j][1], acc[mf][j][2], acc[mf][j][3],
                             aF[mf][0], aF[mf][1], aF[mf][2], aF[mf][3],
                             bF[j >> 1][(j & 1) * 2], bF[j >> 1][(j & 1) * 2 + 1]);
            if (k16 == 0 && pf) stsH(nst, 0);
        }
        if (pf) stsH(nst, 1);
    }

    #pragma unroll
    for (int mf = 0; mf < MT / 16; mf++)
        #pragma unroll
        for (int hr = 0; hr < 2; hr++) {
            const int row = m0 + mf * 16 + gq + hr * 8;
            if (row >= rend) continue;
            #pragma unroll
            for (int j = 0; j < 4; j++) {
                const int col = n0 + nw + j * 8 + tg * 2;
                __half2* dst = (__half2*)(OUT + (size_t)row * H + col);
                *dst = __floats2half2_rn(acc[mf][j][hr * 2 + 0], acc[mf][j][hr * 2 + 1]);
            }
        }
}

__global__ __launch_bounds__(256, 2) void down_gemm(const __half* __restrict__ A,
                                                    const float* __restrict__ W2,
                                                    __half* __restrict__ OUT) {
    extern __shared__ char smem[];
    const int e = blockIdx.y;
    const int n64 = g_n64[e];
    const int bx = blockIdx.x;
    const int rend = g_offsets[e + 1];
    const int n0 = blockIdx.z * 256;
    if (bx < n64) {
        down_tile<64>(smem, A, W2, OUT, e, g_offsets[e] + bx * 64, rend, n0);
    } else if (bx == n64) {
        const int m0 = g_off32[e];
        if (m0 >= 0) down_tile<32>(smem, A, W2, OUT, e, m0, rend, n0);
    }
}

// ---------------- combine: out[t] = sum_k w[t,k] * ybuf[slot_of[t,k]] ----------
__global__ __launch_bounds__(256) void combine_kernel(float* __restrict__ out) {
    const int t = blockIdx.x;
    __shared__ float w[TOPK];
    __shared__ int rowi[TOPK];
    if (threadIdx.x < TOPK) {
        w[threadIdx.x] = g_topk_w[t * TOPK + threadIdx.x];
        rowi[threadIdx.x] = g_slot_of[t * TOPK + threadIdx.x];
    }
    __syncthreads();
    const int j = threadIdx.x;  // 256 threads x 8 outputs = 2048 = H
    float acc[8];
    #pragma unroll
    for (int q = 0; q < 8; q++) acc[q] = 0.f;
    #pragma unroll
    for (int k = 0; k < TOPK; k++) {
        const uint4 v = *(const uint4*)(g_ybuf + (size_t)rowi[k] * H + j * 8);
        const __half2* hp = (const __half2*)&v;
        const float wk = w[k];
        #pragma unroll
        for (int q = 0; q < 4; q++) {
            float2 f = __half22float2(hp[q]);
            acc[2 * q + 0] = fmaf(wk, f.x, acc[2 * q + 0]);
            acc[2 * q + 1] = fmaf(wk, f.y, acc[2 * q + 1]);
        }
    }
    float4* orow = (float4*)(out + (size_t)t * H + j * 8);
    orow[0] = make_float4(acc[0], acc[1], acc[2], acc[3]);
    orow[1] = make_float4(acc[4], acc[5], acc[6], acc[7]);
}

// ---------------- launch ------------------------------------------------------
extern "C" void kernel_launch(void* const* d_in, const int* in_sizes, int n_in,
                              void* d_out, int out_size) {
    const float* x  = (const float*)d_in[0];
    const float* gw = (const float*)d_in[1];
    const float* w1 = (const float*)d_in[2];
    const float* w3 = (const float*)d_in[3];
    const float* w2 = (const float*)d_in[4];
    float* out = (float*)d_out;

    __half *xh, *abuf, *ybuf;
    cudaGetSymbolAddress((void**)&xh, g_xh);
    cudaGetSymbolAddress((void**)&abuf, g_abuf);
    cudaGetSymbolAddress((void**)&ybuf, g_ybuf);

    cudaFuncSetAttribute(up_gemm, cudaFuncAttributeMaxDynamicSharedMemorySize, UP_SMEM);
    cudaFuncSetAttribute(down_gemm, cudaFuncAttributeMaxDynamicSharedMemorySize, DN_SMEM);

    init_kernel<<<1, 64>>>();
    gate_kernel<<<T / 4, 256>>>(x, gw, xh);
    scan_kernel<<<1, 32>>>();
    scatter_kernel<<<(NSLOT + 255) / 256, 256>>>();

    // fused up-proj: act = silu(X@w1) * (X@w3)
    dim3 gridU(8, E, I / 128);
    up_gemm<<<gridU, 256, UP_SMEM>>>(xh, w1, w3, abuf);

    // down-proj: ybuf = act @ w2
    dim3 gridD(8, E, H / 256);
    down_gemm<<<gridD, 256, DN_SMEM>>>(abuf, w2, ybuf);

    combine_kernel<<<T, 256>>>(out);
}